// round 12
// baseline (speedup 1.0000x reference)
#include <cuda_runtime.h>
#include <cuda_fp16.h>
#include <math.h>

#define NB 4
#define SS 64
#define DM 512
#define NH 8
#define DHD 64
#define FF 2048
#define NL 2
#define NV 32128
#define NT 16
#define NEGB (-1e9f)
#define BPT 240
#define BPC 134
#define NLM 251

// ---------------- device scratch (static, no allocs) ----------------------
static __device__ float g_x[NB*SS*DM];
static __device__ float g_h[NB*SS*DM];
static __device__ float g_q[NB*SS*DM];
static __device__ float g_k[NB*SS*DM];
static __device__ float g_v[NB*SS*DM];
static __device__ float g_att[NB*SS*DM];
static __device__ float g_f[NB*SS*FF];
static __device__ float g_hs[NB*SS*DM];
static __device__ float g_gp[4*NB*SS*DM];
static __device__ float g_ck[NL*NB*SS*DM];
static __device__ float g_cv[NL*NB*SS*DM];
static __device__ float g_sk[NL*(NT+1)*NB*DM];
static __device__ float g_sv[NL*(NT+1)*NB*DM];
static __device__ float g_ye[(NT+1)*NB*DM];
static __device__ float g_xd[NB*DM];
static __device__ float g_xd2[NB*DM];
static __device__ float g_qd[NB*DM];
static __device__ float g_fd[NB*FF];
static __device__ float g_lg[NB*NV];
static __device__ float g_vp[4*4*DM];
static __device__ float g_part[BPT*NB*DM];
static __device__ float g_pm[NB*256], g_ps[NB*256];
static __device__ int   g_pi[NB*256];
static __device__ __align__(16) __half g_lmh[(size_t)DM*NV];    // [K][N]
static __device__ __align__(16) __half g_embh[(size_t)NV*DM];   // [V][D]
static __device__ __align__(128) unsigned g_cnt;

struct P {
  const int* ids; const float* mask; const float* emb;
  const float *ewq,*ewk,*ewv,*ewo,*eln1,*ew1,*ew2,*eln2,*elnf;
  const float *dsq,*dsk,*dsv,*dso,*dln1;
  const float *dcq,*dck,*dcv,*dco,*dln2;
  const float *dw1,*dw2,*dln3,*dlnf,*lm;
  float* out; int wp;
};

// ---------------- grid barrier ---------------------------------------------
__device__ __forceinline__ void gbar(int nb, unsigned* sgp) {
  __syncthreads();
  if (threadIdx.x == 0) {
    unsigned tgt = *sgp + (unsigned)nb;
    asm volatile("red.release.gpu.add.u32 [%0], 1;" :: "l"(&g_cnt) : "memory");
    unsigned v;
    do { asm volatile("ld.acquire.gpu.u32 %0, [%1];" : "=r"(v) : "l"(&g_cnt) : "memory"); }
    while ((int)(v - tgt) < 0);
    *sgp = tgt;
  }
  __syncthreads();
}

// ---------------- fp32 -> fp16 conversion ----------------------------------
__device__ void conv1(const float* s, __half* d, size_t n4, int bid, int nb, int tid) {
  const float4* s4 = (const float4*)s;
  uint2* d2 = (uint2*)d;
  for (size_t i = (size_t)bid*256 + tid; i < n4; i += (size_t)nb*256) {
    float4 v = s4[i];
    __half2 h0 = __floats2half2_rn(v.x, v.y), h1 = __floats2half2_rn(v.z, v.w);
    uint2 o; o.x = *(unsigned*)&h0; o.y = *(unsigned*)&h1;
    d2[i] = o;
  }
}

// ---------------- phases ----------------------------------------------------

__device__ void ph_embed(const P& p, int bid, int nb, int tid) {
  for (int r = bid; r < NB*SS; r += nb) {
    int id = p.ids[r];
    const float4* s = (const float4*)(p.emb + (size_t)id*DM);
    float4* d = (float4*)(g_x + (size_t)r*DM);
    for (int i = tid; i < DM/4; i += 256) d[i] = s[i];
  }
  if (bid == 0) {
    for (int i = tid; i < NB*DM; i += 256) g_ye[i] = p.emb[i & (DM-1)];
  }
}

__device__ void ph_rms(const float* x, const float* ln, float* o, int rows,
                       float* sr, int bid, int nb, int tid) {
  const float4* x4 = (const float4*)x;
  const float4* l4 = (const float4*)ln;
  float4* o4 = (float4*)o;
  for (int r = bid; r < rows; r += nb) {
    float s = 0.f;
    for (int i = tid; i < DM/4; i += 256) {
      float4 v = x4[(size_t)r*(DM/4)+i];
      s += v.x*v.x + v.y*v.y + v.z*v.z + v.w*v.w;
    }
    sr[tid] = s; __syncthreads();
    for (int st = 128; st; st >>= 1) { if (tid < st) sr[tid] += sr[tid+st]; __syncthreads(); }
    float sc = rsqrtf(sr[0]*(1.f/DM) + 1e-6f);
    __syncthreads();
    for (int i = tid; i < DM/4; i += 256) {
      float4 v = x4[(size_t)r*(DM/4)+i]; float4 lw = l4[i];
      v.x *= sc*lw.x; v.y *= sc*lw.y; v.z *= sc*lw.z; v.w *= sc*lw.w;
      o4[(size_t)r*(DM/4)+i] = v;
    }
  }
}

// encoder GEMM: 64x64 tile, 4x4 micro-tile, optional K-split to partials
__device__ void ph_gemm(const float* A, const float* const* Ws, float* const* Cs, int nW,
                        int M, int N, int K, int flags, int ksp, float* Cpart,
                        float* sx, int bid, int nb, int tid) {
  int mt = M >> 6, nt = N >> 6;
  int per = mt*nt*ksp;
  int ntasks = nW*per;
  if (bid >= ntasks) return;
  float* As = sx;
  float* Wt = sx + 1024;
  int Klen = K / ksp;
  int tr = tid >> 4, tc = tid & 15;
  int arow = tid >> 2, akq = tid & 3;
  int wkk = tid >> 4, wcc = (tid & 15) << 2;
  for (int t = bid; t < ntasks; t += nb) {
    int wi = t / per, r = t % per;
    int kc = r / (mt*nt); int r2 = r % (mt*nt);
    int m0 = (r2 / nt) << 6, n0 = (r2 % nt) << 6;
    int kb = kc*Klen;
    const float* W = Ws[wi];
    float acc[4][4];
    #pragma unroll
    for (int i = 0; i < 4; i++)
      #pragma unroll
      for (int j = 0; j < 4; j++) acc[i][j] = 0.f;
    for (int kt = 0; kt < Klen; kt += 16) {
      __syncthreads();
      float4 av = *(const float4*)&A[(size_t)(m0+arow)*K + kb + kt + (akq<<2)];
      As[(akq*4+0)*64 + arow] = av.x;
      As[(akq*4+1)*64 + arow] = av.y;
      As[(akq*4+2)*64 + arow] = av.z;
      As[(akq*4+3)*64 + arow] = av.w;
      *(float4*)&Wt[wkk*64 + wcc] = *(const float4*)&W[(size_t)(kb+kt+wkk)*N + n0 + wcc];
      __syncthreads();
      #pragma unroll
      for (int kk = 0; kk < 16; kk++) {
        float4 a = *(const float4*)&As[kk*64 + (tr<<2)];
        float4 w = *(const float4*)&Wt[kk*64 + (tc<<2)];
        acc[0][0]=fmaf(a.x,w.x,acc[0][0]); acc[0][1]=fmaf(a.x,w.y,acc[0][1]);
        acc[0][2]=fmaf(a.x,w.z,acc[0][2]); acc[0][3]=fmaf(a.x,w.w,acc[0][3]);
        acc[1][0]=fmaf(a.y,w.x,acc[1][0]); acc[1][1]=fmaf(a.y,w.y,acc[1][1]);
        acc[1][2]=fmaf(a.y,w.z,acc[1][2]); acc[1][3]=fmaf(a.y,w.w,acc[1][3]);
        acc[2][0]=fmaf(a.z,w.x,acc[2][0]); acc[2][1]=fmaf(a.z,w.y,acc[2][1]);
        acc[2][2]=fmaf(a.z,w.z,acc[2][2]); acc[2][3]=fmaf(a.z,w.w,acc[2][3]);
        acc[3][0]=fmaf(a.w,w.x,acc[3][0]); acc[3][1]=fmaf(a.w,w.y,acc[3][1]);
        acc[3][2]=fmaf(a.w,w.z,acc[3][2]); acc[3][3]=fmaf(a.w,w.w,acc[3][3]);
      }
    }
    #pragma unroll
    for (int i = 0; i < 4; i++) {
      float4 v = make_float4(acc[i][0], acc[i][1], acc[i][2], acc[i][3]);
      if (ksp == 1) {
        if (flags & 1) { v.x=fmaxf(v.x,0.f); v.y=fmaxf(v.y,0.f); v.z=fmaxf(v.z,0.f); v.w=fmaxf(v.w,0.f); }
        float4* cp = (float4*)&Cs[wi][(size_t)(m0+(tr<<2)+i)*N + n0 + (tc<<2)];
        if (flags & 2) { float4 o = *cp; o.x+=v.x; o.y+=v.y; o.z+=v.z; o.w+=v.w; *cp = o; }
        else *cp = v;
      } else {
        *(float4*)&Cpart[((size_t)kc*M + m0+(tr<<2)+i)*N + n0 + (tc<<2)] = v;
      }
    }
  }
}

__device__ void ph_gred(float* C, const float* part, int M, int N, int ksp, int flags,
                        int bid, int nb, int tid) {
  int tot = (M*N) >> 2;
  const float4* p4 = (const float4*)part;
  float4* c4 = (float4*)C;
  for (int i = bid*256+tid; i < tot; i += nb*256) {
    float4 v = p4[i];
    for (int kc = 1; kc < ksp; kc++) {
      float4 u = p4[(size_t)kc*tot + i];
      v.x += u.x; v.y += u.y; v.z += u.z; v.w += u.w;
    }
    if (flags & 1) { v.x=fmaxf(v.x,0.f); v.y=fmaxf(v.y,0.f); v.z=fmaxf(v.z,0.f); v.w=fmaxf(v.w,0.f); }
    if (flags & 2) { float4 o = c4[i]; o.x+=v.x; o.y+=v.y; o.z+=v.z; o.w+=v.w; c4[i] = o; }
    else c4[i] = v;
  }
}

// encoder attention: warp per (query row, head). Tk <= 64.
__device__ void ph_attn(const float* q, const float* kc, const float* vc, float* o,
                        int Tq, int Tk, long long kbs, long long kts,
                        const float* mask, int ntasks,
                        float* sr, int bid, int nb, int tid) {
  int wid = tid >> 5, lane = tid & 31;
  float* ws = sr + wid*128;
  for (int t = bid*8 + wid; t < ntasks; t += nb*8) {
    int h = t & 7, rq = t >> 3, b = rq / Tq;
    const float* qp = q + (size_t)rq*DM + h*DHD;
    ws[lane] = qp[lane]; ws[32+lane] = qp[32+lane];
    __syncwarp();
    float s0 = -3e38f, s1 = -3e38f;
    if (lane < Tk) {
      const float* kp = kc + (size_t)b*kbs + (size_t)lane*kts + h*DHD;
      float d = 0.f;
      #pragma unroll 8
      for (int i = 0; i < DHD; i++) d = fmaf(ws[i], kp[i], d);
      s0 = d*0.125f;
      if (mask) s0 += (1.f - mask[b*SS + lane])*NEGB;
    }
    if (lane+32 < Tk) {
      const float* kp = kc + (size_t)b*kbs + (size_t)(lane+32)*kts + h*DHD;
      float d = 0.f;
      #pragma unroll 8
      for (int i = 0; i < DHD; i++) d = fmaf(ws[i], kp[i], d);
      s1 = d*0.125f;
      if (mask) s1 += (1.f - mask[b*SS + lane+32])*NEGB;
    }
    float m = fmaxf(s0, s1);
    #pragma unroll
    for (int off = 16; off; off >>= 1) m = fmaxf(m, __shfl_xor_sync(0xffffffffu, m, off));
    float e0 = (lane < Tk)    ? expf(s0 - m) : 0.f;
    float e1 = (lane+32 < Tk) ? expf(s1 - m) : 0.f;
    float su = e0 + e1;
    #pragma unroll
    for (int off = 16; off; off >>= 1) su += __shfl_xor_sync(0xffffffffu, su, off);
    __syncwarp();
    ws[64+lane] = e0; ws[96+lane] = e1;
    __syncwarp();
    float inv = 1.f/su;
    float o0 = 0.f, o1 = 0.f;
    const float* vb = vc + (size_t)b*kbs + h*DHD;
    for (int j = 0; j < Tk; j++) {
      float pj = ws[64+j];
      const float* vp = vb + (size_t)j*kts;
      o0 = fmaf(pj, vp[lane], o0);
      o1 = fmaf(pj, vp[32+lane], o1);
    }
    float* op = o + (size_t)rq*DM + h*DHD;
    op[lane] = o0*inv; op[32+lane] = o1*inv;
    __syncwarp();
  }
}

// stage x[4][512] into sx (fp32), with optional vp partial-fold, optional rms(ln),
// optional write-back of x_eff to xwb (xwb MUST differ from x — race-free ping-pong).
__device__ void stage512(const float* x, const float* vp, const float* ln, float* xwb,
                         float* sx, float* sr, int tid) {
  const float4* x4 = (const float4*)x;
  float4* sx4 = (float4*)sx;
  float4 va[2];
  float ss0 = 0.f, ss1 = 0.f;
  #pragma unroll
  for (int pp = 0; pp < 2; pp++) {
    int i = tid + pp*256;
    float4 v = x4[i];
    if (vp) {
      int m = i >> 7, d = i & 127;
      #pragma unroll
      for (int bk = 0; bk < 4; bk++) {
        float4 u = ((const float4*)vp)[(bk*4+m)*128 + d];
        v.x += u.x; v.y += u.y; v.z += u.z; v.w += u.w;
      }
    }
    if (xwb) ((float4*)xwb)[i] = v;
    va[pp] = v;
    float s = v.x*v.x + v.y*v.y + v.z*v.z + v.w*v.w;
    if (pp == 0) ss0 = s; else ss1 = s;
  }
  if (ln) {
    #pragma unroll
    for (int off = 16; off; off >>= 1) {
      ss0 += __shfl_xor_sync(0xffffffffu, ss0, off);
      ss1 += __shfl_xor_sync(0xffffffffu, ss1, off);
    }
    int wid = tid >> 5, lane = tid & 31;
    if (lane == 0) { sr[wid] = ss0; sr[8+wid] = ss1; }
    __syncthreads();
    const float4* ln4 = (const float4*)ln;
    #pragma unroll
    for (int pp = 0; pp < 2; pp++) {
      int i = tid + pp*256;
      int m = i >> 7, d = i & 127;
      float sum = sr[m*4] + sr[m*4+1] + sr[m*4+2] + sr[m*4+3];
      float sc = rsqrtf(sum*(1.f/DM) + 1e-6f);
      float4 lw = ln4[d];
      float4 v = va[pp];
      v.x *= sc*lw.x; v.y *= sc*lw.y; v.z *= sc*lw.z; v.w *= sc*lw.w;
      sx4[i] = v;
    }
  } else {
    sx4[tid] = va[0]; sx4[tid+256] = va[1];
  }
  __syncthreads();
}

// shared GEMV tail: x staged in sx[4][K], compute one 16-col tile tn
__device__ __forceinline__ void gemv_tile(const float* sx, const float* W, float* out,
                                          int N, int K, int flags, int tn, int kb0,
                                          float* sr, int tid) {
  int c = tid & 3, ksl = tid >> 2;
  int KS = K >> 6;
  int N4 = N >> 2, w8 = tid >> 5;
  float4* sr4 = (float4*)sr;
  int kb = kb0 + ksl*KS;
  const float4* wp = (const float4*)W + (size_t)kb*N4 + tn*4 + c;
  float4 a[4];
  #pragma unroll
  for (int m = 0; m < 4; m++) a[m] = make_float4(0,0,0,0);
  #pragma unroll 8
  for (int kk = 0; kk < KS; kk++) {
    float4 w = wp[(size_t)kk*N4];
    #pragma unroll
    for (int m = 0; m < 4; m++) {
      float xv = sx[m*K + kb - kb0 + kk];
      a[m].x = fmaf(xv, w.x, a[m].x);
      a[m].y = fmaf(xv, w.y, a[m].y);
      a[m].z = fmaf(xv, w.z, a[m].z);
      a[m].w = fmaf(xv, w.w, a[m].w);
    }
  }
  #pragma unroll
  for (int off = 4; off <= 16; off <<= 1) {
    #pragma unroll
    for (int m = 0; m < 4; m++) {
      a[m].x += __shfl_xor_sync(0xffffffffu, a[m].x, off);
      a[m].y += __shfl_xor_sync(0xffffffffu, a[m].y, off);
      a[m].z += __shfl_xor_sync(0xffffffffu, a[m].z, off);
      a[m].w += __shfl_xor_sync(0xffffffffu, a[m].w, off);
    }
  }
  if ((ksl & 7) == 0) {
    #pragma unroll
    for (int m = 0; m < 4; m++) sr4[(w8*4 + c)*4 + m] = a[m];
  }
  __syncthreads();
  if (tid < 16) {
    int cc = tid & 3, m = tid >> 2;
    float4 v = sr4[cc*4 + m];
    #pragma unroll
    for (int w = 1; w < 8; w++) {
      float4 u = sr4[(w*4+cc)*4 + m];
      v.x += u.x; v.y += u.y; v.z += u.z; v.w += u.w;
    }
    if (flags & 1) { v.x=fmaxf(v.x,0.f); v.y=fmaxf(v.y,0.f); v.z=fmaxf(v.z,0.f); v.w=fmaxf(v.w,0.f); }
    float4* op = (float4*)(out + (size_t)m*N) + tn*4 + cc;
    if (flags & 2) { float4 o = *op; o.x+=v.x; o.y+=v.y; o.z+=v.z; o.w+=v.w; *op = o; }
    else *op = v;
  }
  __syncthreads();
}

// decode GEMV (fp32 weights): 16-col tiles, 64-way in-block K-split,
// optional block K-split to partials, optional vp-fold + xwb on staging.
__device__ void ph_gemv(const float* x, const float* vp, float* xwb,
                        const float* const* Ws, float* const* Os, int nW,
                        int N, int K, const float* ln, int flags, int bksp, float* part,
                        float* sx, float* sr, int bid, int nb, int tid) {
  int ntile = N >> 4;
  int per = ntile * bksp;
  int ntasks = nW * per;
  if (bid >= ntasks) return;
  if (K == 512) {
    stage512(x, vp, ln, (bid == 0) ? xwb : nullptr, sx, sr, tid);
  } else {
    const float4* x4 = (const float4*)x;
    float4* sx4 = (float4*)sx;
    for (int i = tid; i < (K >> 2); i += 256) {
      #pragma unroll
      for (int m = 0; m < 4; m++) sx4[m*(K>>2)+i] = x4[m*(K>>2)+i];
    }
    __syncthreads();
  }
  int c = tid & 3, ksl = tid >> 2;
  int KS = K / (bksp << 6);
  int N4 = N >> 2, w8 = tid >> 5;
  float4* sr4 = (float4*)sr;
  for (int t = bid; t < ntasks; t += nb) {
    int wi = t / per, r = t % per;
    int bk = r / ntile, tn = r % ntile;
    int kb = bk*(K/bksp) + ksl*KS;
    const float4* wp = (const float4*)Ws[wi] + (size_t)kb*N4 + tn*4 + c;
    float4 a[4];
    #pragma unroll
    for (int m = 0; m < 4; m++) a[m] = make_float4(0,0,0,0);
    #pragma unroll 8
    for (int kk = 0; kk < KS; kk++) {
      float4 w = wp[(size_t)kk*N4];
      #pragma unroll
      for (int m = 0; m < 4; m++) {
        float xv = sx[m*K + kb + kk];
        a[m].x = fmaf(xv, w.x, a[m].x);
        a[m].y = fmaf(xv, w.y, a[m].y);
        a[m].z = fmaf(xv, w.z, a[m].z);
        a[m].w = fmaf(xv, w.w, a[m].w);
      }
    }
    #pragma unroll
    for (int off = 4; off <= 16; off <<= 1) {
      #pragma unroll
      for (int m = 0; m < 4; m++) {
        a[m].x += __shfl_xor_sync(0xffffffffu, a[m].x, off);
        a[m].y += __shfl_xor_sync(0xffffffffu, a[m].y, off);
        a[m].z += __shfl_xor_sync(0xffffffffu, a[m].z, off);
        a[m].w += __shfl_xor_sync(0xffffffffu, a[m].w, off);
      }
    }
    if ((ksl & 7) == 0) {
      #pragma unroll
      for (int m = 0; m < 4; m++) sr4[(w8*4 + c)*4 + m] = a[m];
    }
    __syncthreads();
    if (tid < 16) {
      int cc = tid & 3, m = tid >> 2;
      float4 v = sr4[cc*4 + m];
      #pragma unroll
      for (int w = 1; w < 8; w++) {
        float4 u = sr4[(w*4+cc)*4 + m];
        v.x += u.x; v.y += u.y; v.z += u.z; v.w += u.w;
      }
      if (bksp == 1) {
        if (flags & 1) { v.x=fmaxf(v.x,0.f); v.y=fmaxf(v.y,0.f); v.z=fmaxf(v.z,0.f); v.w=fmaxf(v.w,0.f); }
        float4* op = (float4*)(Os[wi] + (size_t)m*N) + tn*4 + cc;
        if (flags & 2) { float4 o = *op; o.x+=v.x; o.y+=v.y; o.z+=v.z; o.w+=v.w; *op = o; }
        else *op = v;
      } else {
        ((float4*)(part + ((size_t)(bk*4) + m)*N))[tn*4 + cc] = v;
      }
    }
    __syncthreads();
  }
}

// FUSED decode attention + projection GEMV.
// Each active block (bid < 32) redundantly computes full decode attention
// (q from qg; K/V addressed base + b*kbs + j*kts + h*64) into sx[4][512],
// then runs its 16-col tile of the N=512 projection W -> out (flags semantics as ph_gemv).
__device__ void ph_attn_gemv(const float* qg, const float* kc, const float* vc,
                             int Tk, long long kbs, long long kts, const float* mask,
                             const float* W, float* out, int flags,
                             float* sx, float* sr, int bid, int nb, int tid) {
  if (bid >= 32) return;
  int wid = tid >> 5, lane = tid & 31;
  float* ws = sr + wid*128;
  for (int t = wid; t < 32; t += 8) {
    int h = t & 7, b = t >> 3;
    const float* qp = qg + (size_t)b*DM + h*DHD;
    ws[lane] = qp[lane]; ws[32+lane] = qp[32+lane];
    __syncwarp();
    float s0 = -3e38f, s1 = -3e38f;
    if (lane < Tk) {
      const float* kp = kc + (size_t)b*kbs + (size_t)lane*kts + h*DHD;
      float d = 0.f;
      #pragma unroll 8
      for (int i = 0; i < DHD; i++) d = fmaf(ws[i], kp[i], d);
      s0 = d*0.125f;
      if (mask) s0 += (1.f - mask[b*SS + lane])*NEGB;
    }
    if (lane+32 < Tk) {
      const float* kp = kc + (size_t)b*kbs + (size_t)(lane+32)*kts + h*DHD;
      float d = 0.f;
      #pragma unroll 8
      for (int i = 0; i < DHD; i++) d = fmaf(ws[i], kp[i], d);
      s1 = d*0.125f;
      if (mask) s1 += (1.f - mask[b*SS + lane+32])*NEGB;
    }
    float m = fmaxf(s0, s1);
    #pragma unroll
    for (int off = 16; off; off >>= 1) m = fmaxf(m, __shfl_xor_sync(0xffffffffu, m, off));
    float e0 = (lane < Tk)    ? expf(s0 - m) : 0.f;
    float e1 = (lane+32 < Tk) ? expf(s1 - m) : 0.f;
    float su = e0 + e1;
    #pragma unroll
    for (int off = 16; off; off >>= 1) su += __shfl_xor_sync(0xffffffffu, su, off);
    __syncwarp();
    ws[64+lane] = e0; ws[96+lane] = e1;
    __syncwarp();
    float inv = 1.f/su;
    float o0 = 0.f, o1 = 0.f;
    const float* vb = vc + (size_t)b*kbs + h*DHD;
    for (int j = 0; j < Tk; j++) {
      float pj = ws[64+j];
      const float* vp = vb + (size_t)j*kts;
      o0 = fmaf(pj, vp[lane], o0);
      o1 = fmaf(pj, vp[32+lane], o1);
    }
    sx[b*DM + h*DHD + lane] = o0*inv;
    sx[b*DM + h*DHD + 32 + lane] = o1*inv;
    __syncwarp();
  }
  __syncthreads();
  gemv_tile(sx, W, out, DM, DM, flags, bid, 0, sr, tid);
}

// lm_head GEMV (fp16), fused final RMSNorm + vp-fold + per-chunk softmax stats
__device__ void ph_lmgemv(const float* x, const float* vp, const float* ln,
                          float* sx, float* sr, int bid, int nb, int tid) {
  if (bid >= NLM) return;
  stage512(x, vp, ln, nullptr, sx, sr, tid);
  int c = tid & 15, ks = tid >> 4;
  float* red = sx + 4*DM;          // 2048 floats
  float* red2 = sx + 4*DM + 2048;  // 128 floats
  for (int t = bid; t < NLM; t += nb) {
    int n8 = t*128 + c*8;
    float a[4][8];
    #pragma unroll
    for (int m = 0; m < 4; m++)
      #pragma unroll
      for (int j = 0; j < 8; j++) a[m][j] = 0.f;
    const __half* wb = g_lmh + (size_t)(ks*32)*NV + n8;
    #pragma unroll 8
    for (int kk = 0; kk < 32; kk++) {
      uint4 raw = *(const uint4*)(wb + (size_t)kk*NV);
      float2 f0 = __half22float2(*(__half2*)&raw.x);
      float2 f1 = __half22float2(*(__half2*)&raw.y);
      float2 f2 = __half22float2(*(__half2*)&raw.z);
      float2 f3 = __half22float2(*(__half2*)&raw.w);
      #pragma unroll
      for (int m = 0; m < 4; m++) {
        float xv = sx[m*DM + ks*32 + kk];
        a[m][0] = fmaf(xv, f0.x, a[m][0]); a[m][1] = fmaf(xv, f0.y, a[m][1]);
        a[m][2] = fmaf(xv, f1.x, a[m][2]); a[m][3] = fmaf(xv, f1.y, a[m][3]);
        a[m][4] = fmaf(xv, f2.x, a[m][4]); a[m][5] = fmaf(xv, f2.y, a[m][5]);
        a[m][6] = fmaf(xv, f3.x, a[m][6]); a[m][7] = fmaf(xv, f3.y, a[m][7]);
      }
    }
    #pragma unroll
    for (int m = 0; m < 4; m++) {
      #pragma unroll
      for (int j = 0; j < 8; j++) red[ks*128 + c*8 + j] = a[m][j];
      __syncthreads();
      if (tid < 128) {
        float v = red[tid];
        #pragma unroll
        for (int k2 = 1; k2 < 16; k2++) v += red[k2*128 + tid];
        g_lg[(size_t)m*NV + t*128 + tid] = v;
        red2[tid] = v;
      }
      __syncthreads();
      if (tid < 32) {
        float mx = -3e38f; int mi = 0;
        #pragma unroll
        for (int j = 0; j < 4; j++) {
          float u = red2[j*32 + tid];
          int ui = j*32 + tid;
          if (u > mx || (u == mx && ui < mi)) { mx = u; mi = ui; }
        }
        #pragma unroll
        for (int off = 16; off; off >>= 1) {
          float omx = __shfl_xor_sync(0xffffffffu, mx, off);
          int omi = __shfl_xor_sync(0xffffffffu, mi, off);
          if (omx > mx || (omx == mx && omi < mi)) { mx = omx; mi = omi; }
        }
        if (tid == 0) { sr[64] = mx; ((int*)sr)[65] = mi; }
      }
      __syncthreads();
      float gm = sr[64];
      if (tid < 128) red2[tid] = expf(red2[tid] - gm);
      __syncthreads();
      if (tid < 32) {
        float s = red2[tid] + red2[32+tid] + red2[64+tid] + red2[96+tid];
        #pragma unroll
        for (int off = 16; off; off >>= 1) s += __shfl_xor_sync(0xffffffffu, s, off);
        if (tid == 0) {
          g_pm[m*256 + t] = gm;
          g_ps[m*256 + t] = s;
          g_pi[m*256 + t] = t*128 + ((int*)sr)[65];
        }
      }
      __syncthreads();
    }
  }
}

// merged: combine chunk stats, write probs to out AND backproj partials
__device__ void ph_sm2bp(const P& p, int it, int skipbp,
                         float* sx, float* sr, int bid, int nb, int tid) {
  {
    int w = tid >> 5, lane = tid & 31;
    if (w < 4) {
      float mx = -3e38f; int mi = 0;
      for (int j = lane; j < NLM; j += 32) {
        float u = g_pm[w*256 + j];
        int ui = g_pi[w*256 + j];
        if (u > mx || (u == mx && ui < mi)) { mx = u; mi = ui; }
      }
      #pragma unroll
      for (int off = 16; off; off >>= 1) {
        float omx = __shfl_xor_sync(0xffffffffu, mx, off);
        int omi = __shfl_xor_sync(0xffffffffu, mi, off);
        if (omx > mx || (omx == mx && omi < mi)) { mx = omx; mi = omi; }
      }
      float s = 0.f;
      for (int j = lane; j < NLM; j += 32) s += g_ps[w*256+j]*expf(g_pm[w*256+j] - mx);
      #pragma unroll
      for (int off = 16; off; off >>= 1) s += __shfl_xor_sync(0xffffffffu, s, off);
      if (lane == 0) { sr[512+w] = mx; sr[516+w] = 1.f/s; ((int*)sr)[520+w] = mi; }
    }
  }
  __syncthreads();
  const int CL = NV/16;
  int ntasks = 64 + BPT;
  for (int t = bid; t < ntasks; t += nb) {
    if (t < 64) {
      int b = t >> 4, ch = t & 15;
      float M = sr[512+b], inv = sr[516+b];
      const float* lg = g_lg + (size_t)b*NV + ch*CL;
      float* pd = p.out + ((size_t)b*NT + it)*NV + ch*CL;
      for (int i = tid; i < CL; i += 256) pd[i] = expf(lg[i] - M)*inv;
      if (ch == 0 && tid == 0 && p.wp)
        p.out[(size_t)NB*NT*NV + (size_t)b*NT + it] = (((int*)sr)[520+b] == 0) ? 1.f : 0.f;
    } else if (!skipbp) {
      int tt = t - 64;
      int kb = tt*BPC;
      int klen = NV - kb; if (klen > BPC) klen = BPC;
      if (klen <= 0) continue;
      for (int idx = tid; idx < 4*BPC; idx += 256) {
        int m = idx / BPC, k = idx - m*BPC;
        float v = 0.f;
        if (k < klen) v = expf(g_lg[(size_t)m*NV + kb + k] - sr[512+m]) * sr[516+m];
        sx[m*BPC + k] = v;
      }
      __syncthreads();
      int c = tid & 127, ks = tid >> 7;
      int k0 = ks*67, k1 = k0 + 67; if (k1 > klen) k1 = klen; if (k0 > klen) k0 = klen;
      float4 a[4];
      #pragma unroll
      for (int m = 0; m < 4; m++) a[m] = make_float4(0,0,0,0);
      #pragma unroll 4
      for (int k = k0; k < k1; k++) {
        uint2 raw = *(const uint2*)(g_embh + (size_t)(kb+k)*DM + c*4);
        float2 e0 = __half22float2(*(__half2*)&raw.x);
        float2 e1 = __half22float2(*(__half2*)&raw.y);
        #pragma unroll
        for (int m = 0; m < 4; m++) {
          float pm = sx[m*BPC + k];
          a[m].x = fmaf(pm, e0.x, a[m].x);
          a[m].y = fmaf(pm, e0.y, a[m].y);
          a[m].z = fmaf(pm, e1.x, a[m].z);
          a[m].w = fmaf(pm, e1.y, a[m].w);
        }
      }
      float4* xr4 = (float4*)(sx + 1024);
      if (ks == 1) {
        #pragma unroll
        for (int m = 0; m < 4; m++) xr4[c*4+m] = a[m];
      }
      __syncthreads();
      if (ks == 0) {
        #pragma unroll
        for (int m = 0; m < 4; m++) {
          float4 u = xr4[c*4+m];
          a[m].x += u.x; a[m].y += u.y; a[m].z += u.z; a[m].w += u.w;
          ((float4*)g_part)[(size_t)tt*512 + m*128 + c] = a[m];
        }
      }
      __syncthreads();
    }
  }
}

// reduce BPT backproj partials -> ye[t+1]; one warp per float4 output
__device__ void ph_redye(float* dst, int bid, int nb, int tid) {
  int gw = bid*8 + (tid >> 5), lane = tid & 31;
  if (gw >= 512) return;
  const float4* p4 = (const float4*)g_part;
  float4 v = make_float4(0,0,0,0);
  for (int t = lane; t < BPT; t += 32) {
    float4 u = p4[(size_t)t*512 + gw];
    v.x += u.x; v.y += u.y; v.z += u.z; v.w += u.w;
  }
  #pragma unroll
  for (int off = 16; off; off >>= 1) {
    v.x += __shfl_xor_sync(0xffffffffu, v.x, off);
    v.y += __shfl_xor_sync(0xffffffffu, v.y, off);
    v.z += __shfl_xor_sync(0xffffffffu, v.z, off);
    v.w += __shfl_xor_sync(0xffffffffu, v.w, off);
  }
  if (lane == 0) ((float4*)dst)[gw] = v;
}

// ---------------- the megakernel ------------------------------------------
__global__ void __launch_bounds__(256, 2) mega(P p, int nb) {
  __shared__ float sx[4*FF + 256];  // 33 KB
  __shared__ float sr[1024];        // 4 KB
  __shared__ unsigned sg;
  int tid = threadIdx.x, bid = blockIdx.x;
  if (tid == 0) sg = 0;
  __syncthreads();

  // startup: fp16 conversions (lm + emb) + embedding
  conv1(p.lm,  g_lmh,  (size_t)DM*NV/4, bid, nb, tid);
  conv1(p.emb, g_embh, (size_t)NV*DM/4, bid, nb, tid);
  ph_embed(p, bid, nb, tid);                                          gbar(nb,&sg);

  // ---------------- encoder (fp32) ----------------
  for (int l = 0; l < NL; l++) {
    size_t o2 = (size_t)l*DM*DM, of = (size_t)l*DM*FF;
    ph_rms(g_x, p.eln1 + (size_t)l*DM, g_h, NB*SS, sr, bid, nb, tid); gbar(nb,&sg);
    { const float* Ws[3] = { p.ewq+o2, p.ewk+o2, p.ewv+o2 };
      float* Cs[3] = { g_q, g_k, g_v };
      ph_gemm(g_h, Ws, Cs, 3, NB*SS, DM, DM, 0, 1, nullptr, sx, bid, nb, tid); }
    gbar(nb,&sg);
    ph_attn(g_q, g_k, g_v, g_att, SS, SS, (long long)SS*DM, (long long)DM,
            p.mask, NB*SS*NH, sr, bid, nb, tid);                      gbar(nb,&sg);
    { const float* Ws[1] = { p.ewo+o2 }; float* Cs[1] = { g_x };
      ph_gemm(g_att, Ws, Cs, 1, NB*SS, DM, DM, 2, 1, nullptr, sx, bid, nb, tid); }
    gbar(nb,&sg);
    ph_rms(g_x, p.eln2 + (size_t)l*DM, g_h, NB*SS, sr, bid, nb, tid); gbar(nb,&sg);
    { const float* Ws[1] = { p.ew1+of }; float* Cs[1] = { g_f };
      ph_gemm(g_h, Ws, Cs, 1, NB*SS, FF, DM, 1, 1, nullptr, sx, bid, nb, tid); }
    gbar(nb,&sg);
    { const float* Ws[1] = { p.ew2+of }; float* Cs[1] = { nullptr };
      ph_gemm(g_f, Ws, Cs, 1, NB*SS, DM, FF, 0, 4, g_gp, sx, bid, nb, tid); }
    gbar(nb,&sg);
    ph_gred(g_x, g_gp, NB*SS, DM, 4, 2, bid, nb, tid);                gbar(nb,&sg);
  }
  ph_rms(g_x, p.elnf, g_hs, NB*SS, sr, bid, nb, tid);                 gbar(nb,&sg);
  { const float* Ws[4] = { p.dck, p.dcv, p.dck + (size_t)DM*DM, p.dcv + (size_t)DM*DM };
    float* Cs[4] = { g_ck, g_cv, g_ck + (size_t)NB*SS*DM, g_cv + (size_t)NB*SS*DM };
    ph_gemm(g_hs, Ws, Cs, 4, NB*SS, DM, DM, 0, 1, nullptr, sx, bid, nb, tid); }
  gbar(nb,&sg);

  // ---------------- decoder: 16 incremental KV-cached steps ----------------
  for (int it = 0; it < NT; it++) {
    const float* xin = g_ye + (size_t)it*NB*DM;
    for (int l = 0; l < NL; l++) {
      size_t o2 = (size_t)l*DM*DM, of = (size_t)l*DM*FF;
      const float* lx  = (l == 0) ? xin : g_xd;
      const float* lvp = (l == 0) ? nullptr : g_vp;
      float* xr = (l == 0) ? g_xd : g_xd2;
      { const float* Ws[3] = { p.dsq+o2, p.dsk+o2, p.dsv+o2 };
        float* Os[3] = { g_qd,
                         g_sk + ((size_t)l*(NT+1) + it)*NB*DM,
                         g_sv + ((size_t)l*(NT+1) + it)*NB*DM };
        ph_gemv(lx, lvp, xr, Ws, Os, 3, DM, DM, p.dln1 + (size_t)l*DM,
                0, 1, nullptr, sx, sr, bid, nb, tid); }
      gbar(nb,&sg);
      // fused self-attention + so projection (accumulate into xr)
      ph_attn_gemv(g_qd, g_sk + (size_t)l*(NT+1)*NB*DM, g_sv + (size_t)l*(NT+1)*NB*DM,
                   it+1, (long long)DM, (long long)NB*DM, nullptr,
                   p.dso+o2, xr, 2, sx, sr, bid, nb, tid);
      gbar(nb,&sg);
      { const float* Ws[1] = { p.dcq+o2 }; float* Os[1] = { g_qd };
        ph_gemv(xr, nullptr, nullptr, Ws, Os, 1, DM, DM, p.dln2 + (size_t)l*DM,
                0, 1, nullptr, sx, sr, bid, nb, tid); }
      gbar(nb,&sg);
      // fused cross-attention + co projection (accumulate into xr)
      ph_attn_gemv(g_qd, g_ck + (size_t)l*NB*SS*DM, g_cv + (size_t)l*NB*SS*DM,
                   SS, (long long)SS*DM, (long long)DM, p.mask,
                   p.dco+o2, xr, 2, sx, sr, bid, nb, tid);
      gbar(nb,&sg);
      { const float* Ws[1] = { p.dw1+of }; float* Os[1] = { g_fd };
        ph_gemv(xr, nullptr, nullptr, Ws, Os, 1, FF, DM, p.dln3 + (size_t)l*DM,
                1, 1, nullptr, sx, sr, bid, nb, tid); }
      gbar(nb,&sg);
      { const float* Ws[1] = { p.dw2+of }; float* Os[1] = { nullptr };
        ph_gemv(g_fd, nullptr, nullptr, Ws, Os, 1, DM, FF, nullptr,
                0, 4, g_vp, sx, sr, bid, nb, tid); }
      gbar(nb,&sg);
    }
    ph_lmgemv(g_xd2, g_vp, p.dlnf, sx, sr, bid, nb, tid);
    gbar(nb,&sg);
    ph_sm2bp(p, it, it == NT-1, sx, sr, bid, nb, tid);
    if (it < NT-1) {
      gbar(nb,&sg);
      ph_redye(g_ye + (size_t)(it+1)*NB*DM, bid, nb, tid);
    }
    gbar(nb,&sg);
  }
  if (bid == 0 && tid == 0) {
    unsigned z = 0;
    asm volatile("st.release.gpu.u32 [%0], %1;" :: "l"(&g_cnt), "r"(z) : "memory");
  }
}

// ---------------- host ------------------------------------------------------
extern "C" void kernel_launch(void* const* d_in, const int* in_sizes, int n_in,
                              void* d_out, int out_size) {
  P p;
  p.ids   = (const int*)  d_in[0];
  p.mask  = (const float*)d_in[1];
  p.emb   = (const float*)d_in[2];
  p.ewq   = (const float*)d_in[3];
  p.ewk   = (const float*)d_in[4];
  p.ewv   = (const float*)d_in[5];
  p.ewo   = (const float*)d_in[6];
  p.eln1  = (const float*)d_in[7];
  p.ew1   = (const float*)d_in[8];
  p.ew2   = (const float*)d_in[9];
  p.eln2  = (const float*)d_in[10];
  p.elnf  = (const float*)d_in[11];
  p.dsq   = (const float*)d_in[12];
  p.dsk   = (const float*)d_in[13];
  p.dsv   = (const float*)d_in[14];
  p.dso   = (const float*)d_in[15];
  p.dln1  = (const float*)d_in[16];
  p.dcq   = (const float*)d_in[17];
  p.dck   = (const float*)d_in[18];
  p.dcv   = (const float*)d_in[19];
  p.dco   = (const float*)d_in[20];
  p.dln2  = (const float*)d_in[21];
  p.dw1   = (const float*)d_in[22];
  p.dw2   = (const float*)d_in[23];
  p.dln3  = (const float*)d_in[24];
  p.dlnf  = (const float*)d_in[25];
  p.lm    = (const float*)d_in[26];
  p.out   = (float*)d_out;
  p.wp    = (out_size > NB*NT*NV) ? 1 : 0;

  int dev = 0; cudaGetDevice(&dev);
  int sms = 0; cudaDeviceGetAttribute(&sms, cudaDevAttrMultiProcessorCount, dev);
  int nb = 2*sms;
  mega<<<nb, 256>>>(p, nb);
}

// round 15
// speedup vs baseline: 1.9343x; 1.9343x over previous
#include <cuda_runtime.h>
#include <cuda_fp16.h>
#include <math.h>

#define NB 4
#define SS 64
#define DM 512
#define NH 8
#define DHD 64
#define FF 2048
#define NL 2
#define NV 32128
#define NT 16
#define NEGB (-1e9f)
#define BPT 240
#define BPC 134
#define NLM 251

// ---------------- device scratch (static, no allocs) ----------------------
static __device__ float g_x[NB*SS*DM];
static __device__ float g_h[NB*SS*DM];
static __device__ float g_q[NB*SS*DM];
static __device__ float g_k[NB*SS*DM];
static __device__ float g_v[NB*SS*DM];
static __device__ float g_att[NB*SS*DM];
static __device__ float g_f[NB*SS*FF];
static __device__ float g_hs[NB*SS*DM];
static __device__ float g_gp[4*NB*SS*DM];
static __device__ float g_ck[NL*NB*SS*DM];
static __device__ float g_cv[NL*NB*SS*DM];
static __device__ float g_sk[NL*(NT+1)*NB*DM];
static __device__ float g_sv[NL*(NT+1)*NB*DM];
static __device__ float g_ye[(NT+1)*NB*DM];
static __device__ float g_xd[NB*DM];
static __device__ float g_xd2[NB*DM];
static __device__ float g_qd[NB*DM];
static __device__ float g_ad[NB*DM];
static __device__ float g_fd[NB*FF];
static __device__ float g_lg[NB*NV];
static __device__ float g_vp[4*4*DM];
static __device__ float g_part[BPT*NB*DM];
static __device__ float g_pm[NB*256], g_ps[NB*256];
static __device__ int   g_pi[NB*256];
static __device__ __align__(16) __half g_lmh[(size_t)DM*NV];    // [K][N]
static __device__ __align__(16) __half g_embh[(size_t)NV*DM];   // [V][D]
static __device__ __align__(128) unsigned g_cnt;

struct P {
  const int* ids; const float* mask; const float* emb;
  const float *ewq,*ewk,*ewv,*ewo,*eln1,*ew1,*ew2,*eln2,*elnf;
  const float *dsq,*dsk,*dsv,*dso,*dln1;
  const float *dcq,*dck,*dcv,*dco,*dln2;
  const float *dw1,*dw2,*dln3,*dlnf,*lm;
  float* out; int wp;
};

// ---------------- grid barrier (clock-paced poll, SM-local pause) ----------
__device__ __forceinline__ void gbar(int nb, unsigned* sgp) {
  __syncthreads();
  if (threadIdx.x == 0) {
    unsigned tgt = *sgp + (unsigned)nb;
    asm volatile("red.release.gpu.add.u32 [%0], 1;" :: "l"(&g_cnt) : "memory");
    unsigned v;
    while (1) {
      asm volatile("ld.acquire.gpu.u32 %0, [%1];" : "=r"(v) : "l"(&g_cnt) : "memory");
      if ((int)(v - tgt) >= 0) break;
      unsigned long long t0 = clock64();
      while (clock64() - t0 < 200ull) { }   // local pause: no L2 traffic
    }
    *sgp = tgt;
  }
  __syncthreads();
}

// ---------------- fp32 -> fp16 conversion ----------------------------------
__device__ void conv1(const float* s, __half* d, size_t n4, int bid, int nb, int tid) {
  const float4* s4 = (const float4*)s;
  uint2* d2 = (uint2*)d;
  for (size_t i = (size_t)bid*256 + tid; i < n4; i += (size_t)nb*256) {
    float4 v = s4[i];
    __half2 h0 = __floats2half2_rn(v.x, v.y), h1 = __floats2half2_rn(v.z, v.w);
    uint2 o; o.x = *(unsigned*)&h0; o.y = *(unsigned*)&h1;
    d2[i] = o;
  }
}

// ---------------- phases ----------------------------------------------------

__device__ void ph_embed(const P& p, int bid, int nb, int tid) {
  for (int r = bid; r < NB*SS; r += nb) {
    int id = p.ids[r];
    const float4* s = (const float4*)(p.emb + (size_t)id*DM);
    float4* d = (float4*)(g_x + (size_t)r*DM);
    for (int i = tid; i < DM/4; i += 256) d[i] = s[i];
  }
  if (bid == 0) {
    for (int i = tid; i < NB*DM; i += 256) g_ye[i] = p.emb[i & (DM-1)];
  }
}

__device__ void ph_rms(const float* x, const float* ln, float* o, int rows,
                       float* sr, int bid, int nb, int tid) {
  const float4* x4 = (const float4*)x;
  const float4* l4 = (const float4*)ln;
  float4* o4 = (float4*)o;
  for (int r = bid; r < rows; r += nb) {
    float s = 0.f;
    for (int i = tid; i < DM/4; i += 256) {
      float4 v = x4[(size_t)r*(DM/4)+i];
      s += v.x*v.x + v.y*v.y + v.z*v.z + v.w*v.w;
    }
    sr[tid] = s; __syncthreads();
    for (int st = 128; st; st >>= 1) { if (tid < st) sr[tid] += sr[tid+st]; __syncthreads(); }
    float sc = rsqrtf(sr[0]*(1.f/DM) + 1e-6f);
    __syncthreads();
    for (int i = tid; i < DM/4; i += 256) {
      float4 v = x4[(size_t)r*(DM/4)+i]; float4 lw = l4[i];
      v.x *= sc*lw.x; v.y *= sc*lw.y; v.z *= sc*lw.z; v.w *= sc*lw.w;
      o4[(size_t)r*(DM/4)+i] = v;
    }
  }
}

// encoder GEMM: 64x64 tile, 4x4 micro-tile, optional K-split to partials
__device__ void ph_gemm(const float* A, const float* const* Ws, float* const* Cs, int nW,
                        int M, int N, int K, int flags, int ksp, float* Cpart,
                        float* sx, int bid, int nb, int tid) {
  int mt = M >> 6, nt = N >> 6;
  int per = mt*nt*ksp;
  int ntasks = nW*per;
  if (bid >= ntasks) return;
  float* As = sx;
  float* Wt = sx + 1024;
  int Klen = K / ksp;
  int tr = tid >> 4, tc = tid & 15;
  int arow = tid >> 2, akq = tid & 3;
  int wkk = tid >> 4, wcc = (tid & 15) << 2;
  for (int t = bid; t < ntasks; t += nb) {
    int wi = t / per, r = t % per;
    int kc = r / (mt*nt); int r2 = r % (mt*nt);
    int m0 = (r2 / nt) << 6, n0 = (r2 % nt) << 6;
    int kb = kc*Klen;
    const float* W = Ws[wi];
    float acc[4][4];
    #pragma unroll
    for (int i = 0; i < 4; i++)
      #pragma unroll
      for (int j = 0; j < 4; j++) acc[i][j] = 0.f;
    for (int kt = 0; kt < Klen; kt += 16) {
      __syncthreads();
      float4 av = *(const float4*)&A[(size_t)(m0+arow)*K + kb + kt + (akq<<2)];
      As[(akq*4+0)*64 + arow] = av.x;
      As[(akq*4+1)*64 + arow] = av.y;
      As[(akq*4+2)*64 + arow] = av.z;
      As[(akq*4+3)*64 + arow] = av.w;
      *(float4*)&Wt[wkk*64 + wcc] = *(const float4*)&W[(size_t)(kb+kt+wkk)*N + n0 + wcc];
      __syncthreads();
      #pragma unroll
      for (int kk = 0; kk < 16; kk++) {
        float4 a = *(const float4*)&As[kk*64 + (tr<<2)];
        float4 w = *(const float4*)&Wt[kk*64 + (tc<<2)];
        acc[0][0]=fmaf(a.x,w.x,acc[0][0]); acc[0][1]=fmaf(a.x,w.y,acc[0][1]);
        acc[0][2]=fmaf(a.x,w.z,acc[0][2]); acc[0][3]=fmaf(a.x,w.w,acc[0][3]);
        acc[1][0]=fmaf(a.y,w.x,acc[1][0]); acc[1][1]=fmaf(a.y,w.y,acc[1][1]);
        acc[1][2]=fmaf(a.y,w.z,acc[1][2]); acc[1][3]=fmaf(a.y,w.w,acc[1][3]);
        acc[2][0]=fmaf(a.z,w.x,acc[2][0]); acc[2][1]=fmaf(a.z,w.y,acc[2][1]);
        acc[2][2]=fmaf(a.z,w.z,acc[2][2]); acc[2][3]=fmaf(a.z,w.w,acc[2][3]);
        acc[3][0]=fmaf(a.w,w.x,acc[3][0]); acc[3][1]=fmaf(a.w,w.y,acc[3][1]);
        acc[3][2]=fmaf(a.w,w.z,acc[3][2]); acc[3][3]=fmaf(a.w,w.w,acc[3][3]);
      }
    }
    #pragma unroll
    for (int i = 0; i < 4; i++) {
      float4 v = make_float4(acc[i][0], acc[i][1], acc[i][2], acc[i][3]);
      if (ksp == 1) {
        if (flags & 1) { v.x=fmaxf(v.x,0.f); v.y=fmaxf(v.y,0.f); v.z=fmaxf(v.z,0.f); v.w=fmaxf(v.w,0.f); }
        float4* cp = (float4*)&Cs[wi][(size_t)(m0+(tr<<2)+i)*N + n0 + (tc<<2)];
        if (flags & 2) { float4 o = *cp; o.x+=v.x; o.y+=v.y; o.z+=v.z; o.w+=v.w; *cp = o; }
        else *cp = v;
      } else {
        *(float4*)&Cpart[((size_t)kc*M + m0+(tr<<2)+i)*N + n0 + (tc<<2)] = v;
      }
    }
  }
}

__device__ void ph_gred(float* C, const float* part, int M, int N, int ksp, int flags,
                        int bid, int nb, int tid) {
  int tot = (M*N) >> 2;
  const float4* p4 = (const float4*)part;
  float4* c4 = (float4*)C;
  for (int i = bid*256+tid; i < tot; i += nb*256) {
    float4 v = p4[i];
    for (int kc = 1; kc < ksp; kc++) {
      float4 u = p4[(size_t)kc*tot + i];
      v.x += u.x; v.y += u.y; v.z += u.z; v.w += u.w;
    }
    if (flags & 1) { v.x=fmaxf(v.x,0.f); v.y=fmaxf(v.y,0.f); v.z=fmaxf(v.z,0.f); v.w=fmaxf(v.w,0.f); }
    if (flags & 2) { float4 o = c4[i]; o.x+=v.x; o.y+=v.y; o.z+=v.z; o.w+=v.w; c4[i] = o; }
    else c4[i] = v;
  }
}

// attention: warp per (query row, head). Tk <= 64.
__device__ void ph_attn(const float* q, const float* kc, const float* vc, float* o,
                        int Tq, int Tk, long long kbs, long long kts,
                        const float* mask, int ntasks,
                        float* sr, int bid, int nb, int tid) {
  int wid = tid >> 5, lane = tid & 31;
  float* ws = sr + wid*128;
  for (int t = bid*8 + wid; t < ntasks; t += nb*8) {
    int h = t & 7, rq = t >> 3, b = rq / Tq;
    const float* qp = q + (size_t)rq*DM + h*DHD;
    ws[lane] = qp[lane]; ws[32+lane] = qp[32+lane];
    __syncwarp();
    float s0 = -3e38f, s1 = -3e38f;
    if (lane < Tk) {
      const float* kp = kc + (size_t)b*kbs + (size_t)lane*kts + h*DHD;
      float d = 0.f;
      #pragma unroll 8
      for (int i = 0; i < DHD; i++) d = fmaf(ws[i], kp[i], d);
      s0 = d*0.125f;
      if (mask) s0 += (1.f - mask[b*SS + lane])*NEGB;
    }
    if (lane+32 < Tk) {
      const float* kp = kc + (size_t)b*kbs + (size_t)(lane+32)*kts + h*DHD;
      float d = 0.f;
      #pragma unroll 8
      for (int i = 0; i < DHD; i++) d = fmaf(ws[i], kp[i], d);
      s1 = d*0.125f;
      if (mask) s1 += (1.f - mask[b*SS + lane+32])*NEGB;
    }
    float m = fmaxf(s0, s1);
    #pragma unroll
    for (int off = 16; off; off >>= 1) m = fmaxf(m, __shfl_xor_sync(0xffffffffu, m, off));
    float e0 = (lane < Tk)    ? expf(s0 - m) : 0.f;
    float e1 = (lane+32 < Tk) ? expf(s1 - m) : 0.f;
    float su = e0 + e1;
    #pragma unroll
    for (int off = 16; off; off >>= 1) su += __shfl_xor_sync(0xffffffffu, su, off);
    __syncwarp();
    ws[64+lane] = e0; ws[96+lane] = e1;
    __syncwarp();
    float inv = 1.f/su;
    float o0 = 0.f, o1 = 0.f;
    const float* vb = vc + (size_t)b*kbs + h*DHD;
    for (int j = 0; j < Tk; j++) {
      float pj = ws[64+j];
      const float* vp = vb + (size_t)j*kts;
      o0 = fmaf(pj, vp[lane], o0);
      o1 = fmaf(pj, vp[32+lane], o1);
    }
    float* op = o + (size_t)rq*DM + h*DHD;
    op[lane] = o0*inv; op[32+lane] = o1*inv;
    __syncwarp();
  }
}

// stage x[4][512] into sx (fp32), with optional vp partial-fold, optional rms(ln),
// optional write-back of x_eff to xwb (xwb MUST differ from x — race-free ping-pong).
__device__ void stage512(const float* x, const float* vp, const float* ln, float* xwb,
                         float* sx, float* sr, int tid) {
  const float4* x4 = (const float4*)x;
  float4* sx4 = (float4*)sx;
  float4 va[2];
  float ss0 = 0.f, ss1 = 0.f;
  #pragma unroll
  for (int pp = 0; pp < 2; pp++) {
    int i = tid + pp*256;
    float4 v = x4[i];
    if (vp) {
      int m = i >> 7, d = i & 127;
      #pragma unroll
      for (int bk = 0; bk < 4; bk++) {
        float4 u = ((const float4*)vp)[(bk*4+m)*128 + d];
        v.x += u.x; v.y += u.y; v.z += u.z; v.w += u.w;
      }
    }
    if (xwb) ((float4*)xwb)[i] = v;
    va[pp] = v;
    float s = v.x*v.x + v.y*v.y + v.z*v.z + v.w*v.w;
    if (pp == 0) ss0 = s; else ss1 = s;
  }
  if (ln) {
    #pragma unroll
    for (int off = 16; off; off >>= 1) {
      ss0 += __shfl_xor_sync(0xffffffffu, ss0, off);
      ss1 += __shfl_xor_sync(0xffffffffu, ss1, off);
    }
    int wid = tid >> 5, lane = tid & 31;
    if (lane == 0) { sr[wid] = ss0; sr[8+wid] = ss1; }
    __syncthreads();
    const float4* ln4 = (const float4*)ln;
    #pragma unroll
    for (int pp = 0; pp < 2; pp++) {
      int i = tid + pp*256;
      int m = i >> 7, d = i & 127;
      float sum = sr[m*4] + sr[m*4+1] + sr[m*4+2] + sr[m*4+3];
      float sc = rsqrtf(sum*(1.f/DM) + 1e-6f);
      float4 lw = ln4[d];
      float4 v = va[pp];
      v.x *= sc*lw.x; v.y *= sc*lw.y; v.z *= sc*lw.z; v.w *= sc*lw.w;
      sx4[i] = v;
    }
  } else {
    sx4[tid] = va[0]; sx4[tid+256] = va[1];
  }
  __syncthreads();
}

// decode GEMV (fp32 weights): 16-col tiles, 64-way in-block K-split,
// optional block K-split to partials, optional vp-fold + xwb on staging.
__device__ void ph_gemv(const float* x, const float* vp, float* xwb,
                        const float* const* Ws, float* const* Os, int nW,
                        int N, int K, const float* ln, int flags, int bksp, float* part,
                        float* sx, float* sr, int bid, int nb, int tid) {
  int ntile = N >> 4;
  int per = ntile * bksp;
  int ntasks = nW * per;
  if (bid >= ntasks) return;
  if (K == 512) {
    stage512(x, vp, ln, (bid == 0) ? xwb : nullptr, sx, sr, tid);
  } else {
    const float4* x4 = (const float4*)x;
    float4* sx4 = (float4*)sx;
    for (int i = tid; i < (K >> 2); i += 256) {
      #pragma unroll
      for (int m = 0; m < 4; m++) sx4[m*(K>>2)+i] = x4[m*(K>>2)+i];
    }
    __syncthreads();
  }
  int c = tid & 3, ksl = tid >> 2;
  int KS = K / (bksp << 6);
  int N4 = N >> 2, w8 = tid >> 5;
  float4* sr4 = (float4*)sr;
  for (int t = bid; t < ntasks; t += nb) {
    int wi = t / per, r = t % per;
    int bk = r / ntile, tn = r % ntile;
    int kb = bk*(K/bksp) + ksl*KS;
    const float4* wp = (const float4*)Ws[wi] + (size_t)kb*N4 + tn*4 + c;
    float4 a[4];
    #pragma unroll
    for (int m = 0; m < 4; m++) a[m] = make_float4(0,0,0,0);
    #pragma unroll 8
    for (int kk = 0; kk < KS; kk++) {
      float4 w = wp[(size_t)kk*N4];
      #pragma unroll
      for (int m = 0; m < 4; m++) {
        float xv = sx[m*K + kb + kk];
        a[m].x = fmaf(xv, w.x, a[m].x);
        a[m].y = fmaf(xv, w.y, a[m].y);
        a[m].z = fmaf(xv, w.z, a[m].z);
        a[m].w = fmaf(xv, w.w, a[m].w);
      }
    }
    #pragma unroll
    for (int off = 4; off <= 16; off <<= 1) {
      #pragma unroll
      for (int m = 0; m < 4; m++) {
        a[m].x += __shfl_xor_sync(0xffffffffu, a[m].x, off);
        a[m].y += __shfl_xor_sync(0xffffffffu, a[m].y, off);
        a[m].z += __shfl_xor_sync(0xffffffffu, a[m].z, off);
        a[m].w += __shfl_xor_sync(0xffffffffu, a[m].w, off);
      }
    }
    if ((ksl & 7) == 0) {
      #pragma unroll
      for (int m = 0; m < 4; m++) sr4[(w8*4 + c)*4 + m] = a[m];
    }
    __syncthreads();
    if (tid < 16) {
      int cc = tid & 3, m = tid >> 2;
      float4 v = sr4[cc*4 + m];
      #pragma unroll
      for (int w = 1; w < 8; w++) {
        float4 u = sr4[(w*4+cc)*4 + m];
        v.x += u.x; v.y += u.y; v.z += u.z; v.w += u.w;
      }
      if (bksp == 1) {
        if (flags & 1) { v.x=fmaxf(v.x,0.f); v.y=fmaxf(v.y,0.f); v.z=fmaxf(v.z,0.f); v.w=fmaxf(v.w,0.f); }
        float4* op = (float4*)(Os[wi] + (size_t)m*N) + tn*4 + cc;
        if (flags & 2) { float4 o = *op; o.x+=v.x; o.y+=v.y; o.z+=v.z; o.w+=v.w; *op = o; }
        else *op = v;
      } else {
        ((float4*)(part + ((size_t)(bk*4) + m)*N))[tn*4 + cc] = v;
      }
    }
    __syncthreads();
  }
}

// lm_head GEMV (fp16), fused final RMSNorm + vp-fold + per-chunk softmax stats
__device__ void ph_lmgemv(const float* x, const float* vp, const float* ln,
                          float* sx, float* sr, int bid, int nb, int tid) {
  if (bid >= NLM) return;
  stage512(x, vp, ln, nullptr, sx, sr, tid);
  int c = tid & 15, ks = tid >> 4;
  float* red = sx + 4*DM;          // 2048 floats
  float* red2 = sx + 4*DM + 2048;  // 128 floats
  for (int t = bid; t < NLM; t += nb) {
    int n8 = t*128 + c*8;
    float a[4][8];
    #pragma unroll
    for (int m = 0; m < 4; m++)
      #pragma unroll
      for (int j = 0; j < 8; j++) a[m][j] = 0.f;
    const __half* wb = g_lmh + (size_t)(ks*32)*NV + n8;
    #pragma unroll 8
    for (int kk = 0; kk < 32; kk++) {
      uint4 raw = *(const uint4*)(wb + (size_t)kk*NV);
      float2 f0 = __half22float2(*(__half2*)&raw.x);
      float2 f1 = __half22float2(*(__half2*)&raw.y);
      float2 f2 = __half22float2(*(__half2*)&raw.z);
      float2 f3 = __half22float2(*(__half2*)&raw.w);
      #pragma unroll
      for (int m = 0; m < 4; m++) {
        float xv = sx[m*DM + ks*32 + kk];
        a[m][0] = fmaf(xv, f0.x, a[m][0]); a[m][1] = fmaf(xv, f0.y, a[m][1]);
        a[m][2] = fmaf(xv, f1.x, a[m][2]); a[m][3] = fmaf(xv, f1.y, a[m][3]);
        a[m][4] = fmaf(xv, f2.x, a[m][4]); a[m][5] = fmaf(xv, f2.y, a[m][5]);
        a[m][6] = fmaf(xv, f3.x, a[m][6]); a[m][7] = fmaf(xv, f3.y, a[m][7]);
      }
    }
    #pragma unroll
    for (int m = 0; m < 4; m++) {
      #pragma unroll
      for (int j = 0; j < 8; j++) red[ks*128 + c*8 + j] = a[m][j];
      __syncthreads();
      if (tid < 128) {
        float v = red[tid];
        #pragma unroll
        for (int k2 = 1; k2 < 16; k2++) v += red[k2*128 + tid];
        g_lg[(size_t)m*NV + t*128 + tid] = v;
        red2[tid] = v;
      }
      __syncthreads();
      if (tid < 32) {
        float mx = -3e38f; int mi = 0;
        #pragma unroll
        for (int j = 0; j < 4; j++) {
          float u = red2[j*32 + tid];
          int ui = j*32 + tid;
          if (u > mx || (u == mx && ui < mi)) { mx = u; mi = ui; }
        }
        #pragma unroll
        for (int off = 16; off; off >>= 1) {
          float omx = __shfl_xor_sync(0xffffffffu, mx, off);
          int omi = __shfl_xor_sync(0xffffffffu, mi, off);
          if (omx > mx || (omx == mx && omi < mi)) { mx = omx; mi = omi; }
        }
        if (tid == 0) { sr[64] = mx; ((int*)sr)[65] = mi; }
      }
      __syncthreads();
      float gm = sr[64];
      if (tid < 128) red2[tid] = expf(red2[tid] - gm);
      __syncthreads();
      if (tid < 32) {
        float s = red2[tid] + red2[32+tid] + red2[64+tid] + red2[96+tid];
        #pragma unroll
        for (int off = 16; off; off >>= 1) s += __shfl_xor_sync(0xffffffffu, s, off);
        if (tid == 0) {
          g_pm[m*256 + t] = gm;
          g_ps[m*256 + t] = s;
          g_pi[m*256 + t] = t*128 + ((int*)sr)[65];
        }
      }
      __syncthreads();
    }
  }
}

// merged: combine chunk stats, write probs to out AND backproj partials
__device__ void ph_sm2bp(const P& p, int it, int skipbp,
                         float* sx, float* sr, int bid, int nb, int tid) {
  {
    int w = tid >> 5, lane = tid & 31;
    if (w < 4) {
      float mx = -3e38f; int mi = 0;
      for (int j = lane; j < NLM; j += 32) {
        float u = g_pm[w*256 + j];
        int ui = g_pi[w*256 + j];
        if (u > mx || (u == mx && ui < mi)) { mx = u; mi = ui; }
      }
      #pragma unroll
      for (int off = 16; off; off >>= 1) {
        float omx = __shfl_xor_sync(0xffffffffu, mx, off);
        int omi = __shfl_xor_sync(0xffffffffu, mi, off);
        if (omx > mx || (omx == mx && omi < mi)) { mx = omx; mi = omi; }
      }
      float s = 0.f;
      for (int j = lane; j < NLM; j += 32) s += g_ps[w*256+j]*expf(g_pm[w*256+j] - mx);
      #pragma unroll
      for (int off = 16; off; off >>= 1) s += __shfl_xor_sync(0xffffffffu, s, off);
      if (lane == 0) { sr[512+w] = mx; sr[516+w] = 1.f/s; ((int*)sr)[520+w] = mi; }
    }
  }
  __syncthreads();
  const int CL = NV/16;
  int ntasks = 64 + BPT;
  for (int t = bid; t < ntasks; t += nb) {
    if (t < 64) {
      int b = t >> 4, ch = t & 15;
      float M = sr[512+b], inv = sr[516+b];
      const float* lg = g_lg + (size_t)b*NV + ch*CL;
      float* pd = p.out + ((size_t)b*NT + it)*NV + ch*CL;
      for (int i = tid; i < CL; i += 256) pd[i] = expf(lg[i] - M)*inv;
      if (ch == 0 && tid == 0 && p.wp)
        p.out[(size_t)NB*NT*NV + (size_t)b*NT + it] = (((int*)sr)[520+b] == 0) ? 1.f : 0.f;
    } else if (!skipbp) {
      int tt = t - 64;
      int kb = tt*BPC;
      int klen = NV - kb; if (klen > BPC) klen = BPC;
      if (klen <= 0) continue;
      for (int idx = tid; idx < 4*BPC; idx += 256) {
        int m = idx / BPC, k = idx - m*BPC;
        float v = 0.f;
        if (k < klen) v = expf(g_lg[(size_t)m*NV + kb + k] - sr[512+m]) * sr[516+m];
        sx[m*BPC + k] = v;
      }
      __syncthreads();
      int c = tid & 127, ks = tid >> 7;
      int k0 = ks*67, k1 = k0 + 67; if (k1 > klen) k1 = klen; if (k0 > klen) k0 = klen;
      float4 a[4];
      #pragma unroll
      for (int m = 0; m < 4; m++) a[m] = make_float4(0,0,0,0);
      #pragma unroll 4
      for (int k = k0; k < k1; k++) {
        uint2 raw = *(const uint2*)(g_embh + (size_t)(kb+k)*DM + c*4);
        float2 e0 = __half22float2(*(__half2*)&raw.x);
        float2 e1 = __half22float2(*(__half2*)&raw.y);
        #pragma unroll
        for (int m = 0; m < 4; m++) {
          float pm = sx[m*BPC + k];
          a[m].x = fmaf(pm, e0.x, a[m].x);
          a[m].y = fmaf(pm, e0.y, a[m].y);
          a[m].z = fmaf(pm, e1.x, a[m].z);
          a[m].w = fmaf(pm, e1.y, a[m].w);
        }
      }
      float4* xr4 = (float4*)(sx + 1024);
      if (ks == 1) {
        #pragma unroll
        for (int m = 0; m < 4; m++) xr4[c*4+m] = a[m];
      }
      __syncthreads();
      if (ks == 0) {
        #pragma unroll
        for (int m = 0; m < 4; m++) {
          float4 u = xr4[c*4+m];
          a[m].x += u.x; a[m].y += u.y; a[m].z += u.z; a[m].w += u.w;
          ((float4*)g_part)[(size_t)tt*512 + m*128 + c] = a[m];
        }
      }
      __syncthreads();
    }
  }
}

// reduce BPT backproj partials -> ye[t+1]; one warp per float4 output
__device__ void ph_redye(float* dst, int bid, int nb, int tid) {
  int gw = bid*8 + (tid >> 5), lane = tid & 31;
  if (gw >= 512) return;
  const float4* p4 = (const float4*)g_part;
  float4 v = make_float4(0,0,0,0);
  for (int t = lane; t < BPT; t += 32) {
    float4 u = p4[(size_t)t*512 + gw];
    v.x += u.x; v.y += u.y; v.z += u.z; v.w += u.w;
  }
  #pragma unroll
  for (int off = 16; off; off >>= 1) {
    v.x += __shfl_xor_sync(0xffffffffu, v.x, off);
    v.y += __shfl_xor_sync(0xffffffffu, v.y, off);
    v.z += __shfl_xor_sync(0xffffffffu, v.z, off);
    v.w += __shfl_xor_sync(0xffffffffu, v.w, off);
  }
  if (lane == 0) ((float4*)dst)[gw] = v;
}

// ---------------- the megakernel ------------------------------------------
__global__ void __launch_bounds__(256, 2) mega(P p, int nb) {
  __shared__ float sx[4*FF + 256];  // 33 KB
  __shared__ float sr[1024];        // 4 KB
  __shared__ unsigned sg;
  int tid = threadIdx.x, bid = blockIdx.x;
  if (tid == 0) sg = 0;
  __syncthreads();

  // startup: fp16 conversions (lm + emb) + embedding
  conv1(p.lm,  g_lmh,  (size_t)DM*NV/4, bid, nb, tid);
  conv1(p.emb, g_embh, (size_t)NV*DM/4, bid, nb, tid);
  ph_embed(p, bid, nb, tid);                                          gbar(nb,&sg);

  // ---------------- encoder (fp32) ----------------
  for (int l = 0; l < NL; l++) {
    size_t o2 = (size_t)l*DM*DM, of = (size_t)l*DM*FF;
    ph_rms(g_x, p.eln1 + (size_t)l*DM, g_h, NB*SS, sr, bid, nb, tid); gbar(nb,&sg);
    { const float* Ws[3] = { p.ewq+o2, p.ewk+o2, p.ewv+o2 };
      float* Cs[3] = { g_q, g_k, g_v };
      ph_gemm(g_h, Ws, Cs, 3, NB*SS, DM, DM, 0, 1, nullptr, sx, bid, nb, tid); }
    gbar(nb,&sg);
    ph_attn(g_q, g_k, g_v, g_att, SS, SS, (long long)SS*DM, (long long)DM,
            p.mask, NB*SS*NH, sr, bid, nb, tid);                      gbar(nb,&sg);
    { const float* Ws[1] = { p.ewo+o2 }; float* Cs[1] = { g_x };
      ph_gemm(g_att, Ws, Cs, 1, NB*SS, DM, DM, 2, 1, nullptr, sx, bid, nb, tid); }
    gbar(nb,&sg);
    ph_rms(g_x, p.eln2 + (size_t)l*DM, g_h, NB*SS, sr, bid, nb, tid); gbar(nb,&sg);
    { const float* Ws[1] = { p.ew1+of }; float* Cs[1] = { g_f };
      ph_gemm(g_h, Ws, Cs, 1, NB*SS, FF, DM, 1, 1, nullptr, sx, bid, nb, tid); }
    gbar(nb,&sg);
    { const float* Ws[1] = { p.ew2+of }; float* Cs[1] = { nullptr };
      ph_gemm(g_f, Ws, Cs, 1, NB*SS, DM, FF, 0, 4, g_gp, sx, bid, nb, tid); }
    gbar(nb,&sg);
    ph_gred(g_x, g_gp, NB*SS, DM, 4, 2, bid, nb, tid);                gbar(nb,&sg);
  }
  ph_rms(g_x, p.elnf, g_hs, NB*SS, sr, bid, nb, tid);                 gbar(nb,&sg);
  { const float* Ws[4] = { p.dck, p.dcv, p.dck + (size_t)DM*DM, p.dcv + (size_t)DM*DM };
    float* Cs[4] = { g_ck, g_cv, g_ck + (size_t)NB*SS*DM, g_cv + (size_t)NB*SS*DM };
    ph_gemm(g_hs, Ws, Cs, 4, NB*SS, DM, DM, 0, 1, nullptr, sx, bid, nb, tid); }
  gbar(nb,&sg);

  // ---------------- decoder: 16 incremental KV-cached steps ----------------
  for (int it = 0; it < NT; it++) {
    const float* xin = g_ye + (size_t)it*NB*DM;
    for (int l = 0; l < NL; l++) {
      size_t o2 = (size_t)l*DM*DM, of = (size_t)l*DM*FF;
      const float* lx  = (l == 0) ? xin : g_xd;
      const float* lvp = (l == 0) ? nullptr : g_vp;
      float* xr = (l == 0) ? g_xd : g_xd2;
      { const float* Ws[3] = { p.dsq+o2, p.dsk+o2, p.dsv+o2 };
        float* Os[3] = { g_qd,
                         g_sk + ((size_t)l*(NT+1) + it)*NB*DM,
                         g_sv + ((size_t)l*(NT+1) + it)*NB*DM };
        ph_gemv(lx, lvp, xr, Ws, Os, 3, DM, DM, p.dln1 + (size_t)l*DM,
                0, 1, nullptr, sx, sr, bid, nb, tid); }
      gbar(nb,&sg);
      ph_attn(g_qd, g_sk + (size_t)l*(NT+1)*NB*DM, g_sv + (size_t)l*(NT+1)*NB*DM,
              g_ad, 1, it+1, (long long)DM, (long long)NB*DM, nullptr,
              NB*NH, sr, bid, nb, tid);
      gbar(nb,&sg);
      { const float* Ws[1] = { p.dso+o2 }; float* Os[1] = { xr };
        ph_gemv(g_ad, nullptr, nullptr, Ws, Os, 1, DM, DM, nullptr,
                2, 1, nullptr, sx, sr, bid, nb, tid); }
      gbar(nb,&sg);
      { const float* Ws[1] = { p.dcq+o2 }; float* Os[1] = { g_qd };
        ph_gemv(xr, nullptr, nullptr, Ws, Os, 1, DM, DM, p.dln2 + (size_t)l*DM,
                0, 1, nullptr, sx, sr, bid, nb, tid); }
      gbar(nb,&sg);
      ph_attn(g_qd, g_ck + (size_t)l*NB*SS*DM, g_cv + (size_t)l*NB*SS*DM,
              g_ad, 1, SS, (long long)SS*DM, (long long)DM, p.mask,
              NB*NH, sr, bid, nb, tid);
      gbar(nb,&sg);
      { const float* Ws[1] = { p.dco+o2 }; float* Os[1] = { xr };
        ph_gemv(g_ad, nullptr, nullptr, Ws, Os, 1, DM, DM, nullptr,
                2, 1, nullptr, sx, sr, bid, nb, tid); }
      gbar(nb,&sg);
      { const float* Ws[1] = { p.dw1+of }; float* Os[1] = { g_fd };
        ph_gemv(xr, nullptr, nullptr, Ws, Os, 1, FF, DM, p.dln3 + (size_t)l*DM,
                1, 1, nullptr, sx, sr, bid, nb, tid); }
      gbar(nb,&sg);
      { const float* Ws[1] = { p.dw2+of }; float* Os[1] = { nullptr };
        ph_gemv(g_fd, nullptr, nullptr, Ws, Os, 1, DM, FF, nullptr,
                0, 4, g_vp, sx, sr, bid, nb, tid); }
      gbar(nb,&sg);
    }
    ph_lmgemv(g_xd2, g_vp, p.dlnf, sx, sr, bid, nb, tid);
    gbar(nb,&sg);
    ph_sm2bp(p, it, it == NT-1, sx, sr, bid, nb, tid);
    if (it < NT-1) {
      gbar(nb,&sg);
      ph_redye(g_ye + (size_t)(it+1)*NB*DM, bid, nb, tid);
    }
    gbar(nb,&sg);
  }
  if (bid == 0 && tid == 0) {
    unsigned z = 0;
    asm volatile("st.release.gpu.u32 [%0], %1;" :: "l"(&g_cnt), "r"(z) : "memory");
  }
}

// ---------------- host ------------------------------------------------------
extern "C" void kernel_launch(void* const* d_in, const int* in_sizes, int n_in,
                              void* d_out, int out_size) {
  P p;
  p.ids   = (const int*)  d_in[0];
  p.mask  = (const float*)d_in[1];
  p.emb   = (const float*)d_in[2];
  p.ewq   = (const float*)d_in[3];
  p.ewk   = (const float*)d_in[4];
  p.ewv   = (const float*)d_in[5];
  p.ewo   = (const float*)d_in[6];
  p.eln1  = (const float*)d_in[7];
  p.ew1   = (const float*)d_in[8];
  p.ew2   = (const float*)d_in[9];
  p.eln2  = (const float*)d_in[10];
  p.elnf  = (const float*)d_in[11];
  p.dsq   = (const float*)d_in[12];
  p.dsk   = (const float*)d_in[13];
  p.dsv   = (const float*)d_in[14];
  p.dso   = (const float*)d_in[15];
  p.dln1  = (const float*)d_in[16];
  p.dcq   = (const float*)d_in[17];
  p.dck   = (const float*)d_in[18];
  p.dcv   = (const float*)d_in[19];
  p.dco   = (const float*)d_in[20];
  p.dln2  = (const float*)d_in[21];
  p.dw1   = (const float*)d_in[22];
  p.dw2   = (const float*)d_in[23];
  p.dln3  = (const float*)d_in[24];
  p.dlnf  = (const float*)d_in[25];
  p.lm    = (const float*)d_in[26];
  p.out   = (float*)d_out;
  p.wp    = (out_size > NB*NT*NV) ? 1 : 0;

  int dev = 0; cudaGetDevice(&dev);
  int sms = 0; cudaDeviceGetAttribute(&sms, cudaDevAttrMultiProcessorCount, dev);
  int nb = 2*sms;
  mega<<<nb, 256>>>(p, nb);
}

// round 16
// speedup vs baseline: 2.0221x; 1.0454x over previous
#include <cuda_runtime.h>
#include <cuda_fp16.h>
#include <math.h>

#define NB 4
#define SS 64
#define DM 512
#define NH 8
#define DHD 64
#define FF 2048
#define NL 2
#define NV 32128
#define NT 16
#define NEGB (-1e9f)
#define BPT 240
#define BPC 134
#define NLM 251

// ---------------- device scratch (static, no allocs) ----------------------
static __device__ float g_x[NB*SS*DM];
static __device__ float g_h[NB*SS*DM];
static __device__ float g_q[NB*SS*DM];
static __device__ float g_k[NB*SS*DM];
static __device__ float g_v[NB*SS*DM];
static __device__ float g_att[NB*SS*DM];
static __device__ float g_f[NB*SS*FF];
static __device__ float g_hs[NB*SS*DM];
static __device__ float g_gp[4*NB*SS*DM];
static __device__ float g_ck[NL*NB*SS*DM];
static __device__ float g_cv[NL*NB*SS*DM];
static __device__ float g_sk[NL*(NT+1)*NB*DM];
static __device__ float g_sv[NL*(NT+1)*NB*DM];
static __device__ float g_ye[(NT+1)*NB*DM];
static __device__ float g_xd[NB*DM];
static __device__ float g_xd2[NB*DM];
static __device__ float g_xd3[NB*DM];
static __device__ float g_qd[NB*DM];
static __device__ float g_fd[NB*FF];
static __device__ float g_lg[NB*NV];
static __device__ float g_vp[4*4*DM];          // w2 block-ksplit partials [4][4][512]
static __device__ float g_sop[8*4*DM];         // attn->proj head partials [8][4][512]
static __device__ float g_part[BPT*NB*DM];
static __device__ float g_pm[NB*256], g_ps[NB*256];
static __device__ int   g_pi[NB*256];
static __device__ __align__(16) __half g_lmh[(size_t)DM*NV];    // [K][N]
static __device__ __align__(16) __half g_embh[(size_t)NV*DM];   // [V][D]
static __device__ __align__(128) unsigned g_cnt;

struct P {
  const int* ids; const float* mask; const float* emb;
  const float *ewq,*ewk,*ewv,*ewo,*eln1,*ew1,*ew2,*eln2,*elnf;
  const float *dsq,*dsk,*dsv,*dso,*dln1;
  const float *dcq,*dck,*dcv,*dco,*dln2;
  const float *dw1,*dw2,*dln3,*dlnf,*lm;
  float* out; int wp;
};

// ---------------- grid barrier (clock-paced poll) ---------------------------
__device__ __forceinline__ void gbar(int nb, unsigned* sgp) {
  __syncthreads();
  if (threadIdx.x == 0) {
    unsigned tgt = *sgp + (unsigned)nb;
    asm volatile("red.release.gpu.add.u32 [%0], 1;" :: "l"(&g_cnt) : "memory");
    unsigned v;
    while (1) {
      asm volatile("ld.acquire.gpu.u32 %0, [%1];" : "=r"(v) : "l"(&g_cnt) : "memory");
      if ((int)(v - tgt) >= 0) break;
      unsigned long long t0 = clock64();
      while (clock64() - t0 < 200ull) { }
    }
    *sgp = tgt;
  }
  __syncthreads();
}

// ---------------- fp32 -> fp16 conversion ----------------------------------
__device__ void conv1(const float* s, __half* d, size_t n4, int bid, int nb, int tid) {
  const float4* s4 = (const float4*)s;
  uint2* d2 = (uint2*)d;
  for (size_t i = (size_t)bid*256 + tid; i < n4; i += (size_t)nb*256) {
    float4 v = s4[i];
    __half2 h0 = __floats2half2_rn(v.x, v.y), h1 = __floats2half2_rn(v.z, v.w);
    uint2 o; o.x = *(unsigned*)&h0; o.y = *(unsigned*)&h1;
    d2[i] = o;
  }
}

// ---------------- phases ----------------------------------------------------

__device__ void ph_embed(const P& p, int bid, int nb, int tid) {
  for (int r = bid; r < NB*SS; r += nb) {
    int id = p.ids[r];
    const float4* s = (const float4*)(p.emb + (size_t)id*DM);
    float4* d = (float4*)(g_x + (size_t)r*DM);
    for (int i = tid; i < DM/4; i += 256) d[i] = s[i];
  }
  if (bid == 0) {
    for (int i = tid; i < NB*DM; i += 256) g_ye[i] = p.emb[i & (DM-1)];
  }
}

__device__ void ph_rms(const float* x, const float* ln, float* o, int rows,
                       float* sr, int bid, int nb, int tid) {
  const float4* x4 = (const float4*)x;
  const float4* l4 = (const float4*)ln;
  float4* o4 = (float4*)o;
  for (int r = bid; r < rows; r += nb) {
    float s = 0.f;
    for (int i = tid; i < DM/4; i += 256) {
      float4 v = x4[(size_t)r*(DM/4)+i];
      s += v.x*v.x + v.y*v.y + v.z*v.z + v.w*v.w;
    }
    sr[tid] = s; __syncthreads();
    for (int st = 128; st; st >>= 1) { if (tid < st) sr[tid] += sr[tid+st]; __syncthreads(); }
    float sc = rsqrtf(sr[0]*(1.f/DM) + 1e-6f);
    __syncthreads();
    for (int i = tid; i < DM/4; i += 256) {
      float4 v = x4[(size_t)r*(DM/4)+i]; float4 lw = l4[i];
      v.x *= sc*lw.x; v.y *= sc*lw.y; v.z *= sc*lw.z; v.w *= sc*lw.w;
      o4[(size_t)r*(DM/4)+i] = v;
    }
  }
}

// encoder GEMM: 64x64 tile, 4x4 micro-tile, optional K-split to partials
__device__ void ph_gemm(const float* A, const float* const* Ws, float* const* Cs, int nW,
                        int M, int N, int K, int flags, int ksp, float* Cpart,
                        float* sx, int bid, int nb, int tid) {
  int mt = M >> 6, nt = N >> 6;
  int per = mt*nt*ksp;
  int ntasks = nW*per;
  if (bid >= ntasks) return;
  float* As = sx;
  float* Wt = sx + 1024;
  int Klen = K / ksp;
  int tr = tid >> 4, tc = tid & 15;
  int arow = tid >> 2, akq = tid & 3;
  int wkk = tid >> 4, wcc = (tid & 15) << 2;
  for (int t = bid; t < ntasks; t += nb) {
    int wi = t / per, r = t % per;
    int kc = r / (mt*nt); int r2 = r % (mt*nt);
    int m0 = (r2 / nt) << 6, n0 = (r2 % nt) << 6;
    int kb = kc*Klen;
    const float* W = Ws[wi];
    float acc[4][4];
    #pragma unroll
    for (int i = 0; i < 4; i++)
      #pragma unroll
      for (int j = 0; j < 4; j++) acc[i][j] = 0.f;
    for (int kt = 0; kt < Klen; kt += 16) {
      __syncthreads();
      float4 av = *(const float4*)&A[(size_t)(m0+arow)*K + kb + kt + (akq<<2)];
      As[(akq*4+0)*64 + arow] = av.x;
      As[(akq*4+1)*64 + arow] = av.y;
      As[(akq*4+2)*64 + arow] = av.z;
      As[(akq*4+3)*64 + arow] = av.w;
      *(float4*)&Wt[wkk*64 + wcc] = *(const float4*)&W[(size_t)(kb+kt+wkk)*N + n0 + wcc];
      __syncthreads();
      #pragma unroll
      for (int kk = 0; kk < 16; kk++) {
        float4 a = *(const float4*)&As[kk*64 + (tr<<2)];
        float4 w = *(const float4*)&Wt[kk*64 + (tc<<2)];
        acc[0][0]=fmaf(a.x,w.x,acc[0][0]); acc[0][1]=fmaf(a.x,w.y,acc[0][1]);
        acc[0][2]=fmaf(a.x,w.z,acc[0][2]); acc[0][3]=fmaf(a.x,w.w,acc[0][3]);
        acc[1][0]=fmaf(a.y,w.x,acc[1][0]); acc[1][1]=fmaf(a.y,w.y,acc[1][1]);
        acc[1][2]=fmaf(a.y,w.z,acc[1][2]); acc[1][3]=fmaf(a.y,w.w,acc[1][3]);
        acc[2][0]=fmaf(a.z,w.x,acc[2][0]); acc[2][1]=fmaf(a.z,w.y,acc[2][1]);
        acc[2][2]=fmaf(a.z,w.z,acc[2][2]); acc[2][3]=fmaf(a.z,w.w,acc[2][3]);
        acc[3][0]=fmaf(a.w,w.x,acc[3][0]); acc[3][1]=fmaf(a.w,w.y,acc[3][1]);
        acc[3][2]=fmaf(a.w,w.z,acc[3][2]); acc[3][3]=fmaf(a.w,w.w,acc[3][3]);
      }
    }
    #pragma unroll
    for (int i = 0; i < 4; i++) {
      float4 v = make_float4(acc[i][0], acc[i][1], acc[i][2], acc[i][3]);
      if (ksp == 1) {
        if (flags & 1) { v.x=fmaxf(v.x,0.f); v.y=fmaxf(v.y,0.f); v.z=fmaxf(v.z,0.f); v.w=fmaxf(v.w,0.f); }
        float4* cp = (float4*)&Cs[wi][(size_t)(m0+(tr<<2)+i)*N + n0 + (tc<<2)];
        if (flags & 2) { float4 o = *cp; o.x+=v.x; o.y+=v.y; o.z+=v.z; o.w+=v.w; *cp = o; }
        else *cp = v;
      } else {
        *(float4*)&Cpart[((size_t)kc*M + m0+(tr<<2)+i)*N + n0 + (tc<<2)] = v;
      }
    }
  }
}

__device__ void ph_gred(float* C, const float* part, int M, int N, int ksp, int flags,
                        int bid, int nb, int tid) {
  int tot = (M*N) >> 2;
  const float4* p4 = (const float4*)part;
  float4* c4 = (float4*)C;
  for (int i = bid*256+tid; i < tot; i += nb*256) {
    float4 v = p4[i];
    for (int kc = 1; kc < ksp; kc++) {
      float4 u = p4[(size_t)kc*tot + i];
      v.x += u.x; v.y += u.y; v.z += u.z; v.w += u.w;
    }
    if (flags & 1) { v.x=fmaxf(v.x,0.f); v.y=fmaxf(v.y,0.f); v.z=fmaxf(v.z,0.f); v.w=fmaxf(v.w,0.f); }
    if (flags & 2) { float4 o = c4[i]; o.x+=v.x; o.y+=v.y; o.z+=v.z; o.w+=v.w; c4[i] = o; }
    else c4[i] = v;
  }
}

// encoder attention: warp per (query row, head). Tk <= 64.
__device__ void ph_attn(const float* q, const float* kc, const float* vc, float* o,
                        int Tq, int Tk, long long kbs, long long kts,
                        const float* mask, int ntasks,
                        float* sr, int bid, int nb, int tid) {
  int wid = tid >> 5, lane = tid & 31;
  float* ws = sr + wid*128;
  for (int t = bid*8 + wid; t < ntasks; t += nb*8) {
    int h = t & 7, rq = t >> 3, b = rq / Tq;
    const float* qp = q + (size_t)rq*DM + h*DHD;
    ws[lane] = qp[lane]; ws[32+lane] = qp[32+lane];
    __syncwarp();
    float s0 = -3e38f, s1 = -3e38f;
    if (lane < Tk) {
      const float* kp = kc + (size_t)b*kbs + (size_t)lane*kts + h*DHD;
      float d = 0.f;
      #pragma unroll 8
      for (int i = 0; i < DHD; i++) d = fmaf(ws[i], kp[i], d);
      s0 = d*0.125f;
      if (mask) s0 += (1.f - mask[b*SS + lane])*NEGB;
    }
    if (lane+32 < Tk) {
      const float* kp = kc + (size_t)b*kbs + (size_t)(lane+32)*kts + h*DHD;
      float d = 0.f;
      #pragma unroll 8
      for (int i = 0; i < DHD; i++) d = fmaf(ws[i], kp[i], d);
      s1 = d*0.125f;
      if (mask) s1 += (1.f - mask[b*SS + lane+32])*NEGB;
    }
    float m = fmaxf(s0, s1);
    #pragma unroll
    for (int off = 16; off; off >>= 1) m = fmaxf(m, __shfl_xor_sync(0xffffffffu, m, off));
    float e0 = (lane < Tk)    ? expf(s0 - m) : 0.f;
    float e1 = (lane+32 < Tk) ? expf(s1 - m) : 0.f;
    float su = e0 + e1;
    #pragma unroll
    for (int off = 16; off; off >>= 1) su += __shfl_xor_sync(0xffffffffu, su, off);
    __syncwarp();
    ws[64+lane] = e0; ws[96+lane] = e1;
    __syncwarp();
    float inv = 1.f/su;
    float o0 = 0.f, o1 = 0.f;
    const float* vb = vc + (size_t)b*kbs + h*DHD;
    for (int j = 0; j < Tk; j++) {
      float pj = ws[64+j];
      const float* vp = vb + (size_t)j*kts;
      o0 = fmaf(pj, vp[lane], o0);
      o1 = fmaf(pj, vp[32+lane], o1);
    }
    float* op = o + (size_t)rq*DM + h*DHD;
    op[lane] = o0*inv; op[32+lane] = o1*inv;
    __syncwarp();
  }
}

// stage x[4][512] into sx (fp32), with optional nvp-way partial-fold
// (vp layout [nvp][4][512]), optional rms(ln), optional write-back of x_eff
// to xwb (xwb MUST differ from x — race-free ping-pong; bid 0 only).
__device__ void stage512(const float* x, const float* vp, int nvp,
                         const float* ln, float* xwb,
                         float* sx, float* sr, int tid) {
  const float4* x4 = (const float4*)x;
  float4* sx4 = (float4*)sx;
  float4 va[2];
  float ss0 = 0.f, ss1 = 0.f;
  #pragma unroll
  for (int pp = 0; pp < 2; pp++) {
    int i = tid + pp*256;
    float4 v = x4[i];
    if (vp) {
      int m = i >> 7, d = i & 127;
      for (int bk = 0; bk < nvp; bk++) {
        float4 u = ((const float4*)vp)[(bk*4+m)*128 + d];
        v.x += u.x; v.y += u.y; v.z += u.z; v.w += u.w;
      }
    }
    if (xwb) ((float4*)xwb)[i] = v;
    va[pp] = v;
    float s = v.x*v.x + v.y*v.y + v.z*v.z + v.w*v.w;
    if (pp == 0) ss0 = s; else ss1 = s;
  }
  if (ln) {
    #pragma unroll
    for (int off = 16; off; off >>= 1) {
      ss0 += __shfl_xor_sync(0xffffffffu, ss0, off);
      ss1 += __shfl_xor_sync(0xffffffffu, ss1, off);
    }
    int wid = tid >> 5, lane = tid & 31;
    if (lane == 0) { sr[wid] = ss0; sr[8+wid] = ss1; }
    __syncthreads();
    const float4* ln4 = (const float4*)ln;
    #pragma unroll
    for (int pp = 0; pp < 2; pp++) {
      int i = tid + pp*256;
      int m = i >> 7, d = i & 127;
      float sum = sr[m*4] + sr[m*4+1] + sr[m*4+2] + sr[m*4+3];
      float sc = rsqrtf(sum*(1.f/DM) + 1e-6f);
      float4 lw = ln4[d];
      float4 v = va[pp];
      v.x *= sc*lw.x; v.y *= sc*lw.y; v.z *= sc*lw.z; v.w *= sc*lw.w;
      sx4[i] = v;
    }
  } else {
    sx4[tid] = va[0]; sx4[tid+256] = va[1];
  }
  __syncthreads();
}

// decode GEMV (fp32 weights): 16-col tiles, 64-way in-block K-split,
// optional block K-split to partials, optional nvp-fold + xwb on staging.
__device__ void ph_gemv(const float* x, const float* vp, int nvp, float* xwb,
                        const float* const* Ws, float* const* Os, int nW,
                        int N, int K, const float* ln, int flags, int bksp, float* part,
                        float* sx, float* sr, int bid, int nb, int tid) {
  int ntile = N >> 4;
  int per = ntile * bksp;
  int ntasks = nW * per;
  if (bid >= ntasks) return;
  if (K == 512) {
    stage512(x, vp, nvp, ln, (bid == 0) ? xwb : nullptr, sx, sr, tid);
  } else {
    const float4* x4 = (const float4*)x;
    float4* sx4 = (float4*)sx;
    for (int i = tid; i < (K >> 2); i += 256) {
      #pragma unroll
      for (int m = 0; m < 4; m++) sx4[m*(K>>2)+i] = x4[m*(K>>2)+i];
    }
    __syncthreads();
  }
  int c = tid & 3, ksl = tid >> 2;
  int KS = K / (bksp << 6);
  int N4 = N >> 2, w8 = tid >> 5;
  float4* sr4 = (float4*)sr;
  for (int t = bid; t < ntasks; t += nb) {
    int wi = t / per, r = t % per;
    int bk = r / ntile, tn = r % ntile;
    int kb = bk*(K/bksp) + ksl*KS;
    const float4* wp = (const float4*)Ws[wi] + (size_t)kb*N4 + tn*4 + c;
    float4 a[4];
    #pragma unroll
    for (int m = 0; m < 4; m++) a[m] = make_float4(0,0,0,0);
    #pragma unroll 8
    for (int kk = 0; kk < KS; kk++) {
      float4 w = wp[(size_t)kk*N4];
      #pragma unroll
      for (int m = 0; m < 4; m++) {
        float xv = sx[m*K + kb + kk];
        a[m].x = fmaf(xv, w.x, a[m].x);
        a[m].y = fmaf(xv, w.y, a[m].y);
        a[m].z = fmaf(xv, w.z, a[m].z);
        a[m].w = fmaf(xv, w.w, a[m].w);
      }
    }
    #pragma unroll
    for (int off = 4; off <= 16; off <<= 1) {
      #pragma unroll
      for (int m = 0; m < 4; m++) {
        a[m].x += __shfl_xor_sync(0xffffffffu, a[m].x, off);
        a[m].y += __shfl_xor_sync(0xffffffffu, a[m].y, off);
        a[m].z += __shfl_xor_sync(0xffffffffu, a[m].z, off);
        a[m].w += __shfl_xor_sync(0xffffffffu, a[m].w, off);
      }
    }
    if ((ksl & 7) == 0) {
      #pragma unroll
      for (int m = 0; m < 4; m++) sr4[(w8*4 + c)*4 + m] = a[m];
    }
    __syncthreads();
    if (tid < 16) {
      int cc = tid & 3, m = tid >> 2;
      float4 v = sr4[cc*4 + m];
      #pragma unroll
      for (int w = 1; w < 8; w++) {
        float4 u = sr4[(w*4+cc)*4 + m];
        v.x += u.x; v.y += u.y; v.z += u.z; v.w += u.w;
      }
      if (bksp == 1) {
        if (flags & 1) { v.x=fmaxf(v.x,0.f); v.y=fmaxf(v.y,0.f); v.z=fmaxf(v.z,0.f); v.w=fmaxf(v.w,0.f); }
        float4* op = (float4*)(Os[wi] + (size_t)m*N) + tn*4 + cc;
        if (flags & 2) { float4 o = *op; o.x+=v.x; o.y+=v.y; o.z+=v.z; o.w+=v.w; *op = o; }
        else *op = v;
      } else {
        ((float4*)(part + ((size_t)(bk*4) + m)*N))[tn*4 + cc] = v;
      }
    }
    __syncthreads();
  }
}

// FUSED decode attention + HEAD-SLICED projection partial.
// Block t=(b,h) (t<32): warp 0 computes attention for its OWN (b,h) only,
// then all 256 threads compute soP[h][b][:] = attnout @ W[h*64:(h+1)*64, :].
// sop layout [8][4][512] — folded by consumer staging (nvp=8).
__device__ void ph_attnso(const float* qg, const float* kc, const float* vc,
                          int Tk, long long kbs, long long kts, const float* mask,
                          const float* W, float* sop,
                          float* sx, float* sr, int bid, int tid) {
  if (bid >= 32) return;
  int b = bid >> 3, h = bid & 7;
  if (tid < 32) {
    int lane = tid;
    const float* qp = qg + (size_t)b*DM + h*DHD;
    sr[lane] = qp[lane]; sr[32+lane] = qp[32+lane];
    __syncwarp();
    float s0 = -3e38f, s1 = -3e38f;
    if (lane < Tk) {
      const float* kp = kc + (size_t)b*kbs + (size_t)lane*kts + h*DHD;
      float d = 0.f;
      #pragma unroll 8
      for (int i = 0; i < DHD; i++) d = fmaf(sr[i], kp[i], d);
      s0 = d*0.125f;
      if (mask) s0 += (1.f - mask[b*SS + lane])*NEGB;
    }
    if (lane+32 < Tk) {
      const float* kp = kc + (size_t)b*kbs + (size_t)(lane+32)*kts + h*DHD;
      float d = 0.f;
      #pragma unroll 8
      for (int i = 0; i < DHD; i++) d = fmaf(sr[i], kp[i], d);
      s1 = d*0.125f;
      if (mask) s1 += (1.f - mask[b*SS + lane+32])*NEGB;
    }
    float m = fmaxf(s0, s1);
    #pragma unroll
    for (int off = 16; off; off >>= 1) m = fmaxf(m, __shfl_xor_sync(0xffffffffu, m, off));
    float e0 = (lane < Tk)    ? expf(s0 - m) : 0.f;
    float e1 = (lane+32 < Tk) ? expf(s1 - m) : 0.f;
    float su = e0 + e1;
    #pragma unroll
    for (int off = 16; off; off >>= 1) su += __shfl_xor_sync(0xffffffffu, su, off);
    __syncwarp();
    sr[64+lane] = e0; sr[96+lane] = e1;
    __syncwarp();
    float inv = 1.f/su;
    float o0 = 0.f, o1 = 0.f;
    const float* vb = vc + (size_t)b*kbs + h*DHD;
    for (int j = 0; j < Tk; j++) {
      float pj = sr[64+j];
      const float* vp = vb + (size_t)j*kts;
      o0 = fmaf(pj, vp[lane], o0);
      o1 = fmaf(pj, vp[32+lane], o1);
    }
    sx[lane] = o0*inv; sx[32+lane] = o1*inv;
  }
  __syncthreads();
  // head-slice partial GEMV: po[:] = att[0..63] @ W[h*64 .. h*64+63][:]
  int c = tid & 127, ks = tid >> 7;   // col float4 0..127, 2-way K split (32 each)
  const float4* wp = (const float4*)W + (size_t)(h*64 + ks*32)*128 + c;
  float4 a = make_float4(0,0,0,0);
  #pragma unroll 8
  for (int k = 0; k < 32; k++) {
    float4 w = wp[(size_t)k*128];
    float xv = sx[ks*32 + k];
    a.x = fmaf(xv, w.x, a.x); a.y = fmaf(xv, w.y, a.y);
    a.z = fmaf(xv, w.z, a.z); a.w = fmaf(xv, w.w, a.w);
  }
  float4* red = (float4*)(sx + 512);
  if (ks == 1) red[c] = a;
  __syncthreads();
  if (ks == 0) {
    float4 u = red[c];
    a.x += u.x; a.y += u.y; a.z += u.z; a.w += u.w;
    ((float4*)(sop + ((size_t)h*4 + b)*DM))[c] = a;
  }
}

// lm_head GEMV (fp16), fused final RMSNorm + vp-fold + per-chunk softmax stats
__device__ void ph_lmgemv(const float* x, const float* vp, const float* ln,
                          float* sx, float* sr, int bid, int nb, int tid) {
  if (bid >= NLM) return;
  stage512(x, vp, 4, ln, nullptr, sx, sr, tid);
  int c = tid & 15, ks = tid >> 4;
  float* red = sx + 4*DM;          // 2048 floats
  float* red2 = sx + 4*DM + 2048;  // 128 floats
  for (int t = bid; t < NLM; t += nb) {
    int n8 = t*128 + c*8;
    float a[4][8];
    #pragma unroll
    for (int m = 0; m < 4; m++)
      #pragma unroll
      for (int j = 0; j < 8; j++) a[m][j] = 0.f;
    const __half* wb = g_lmh + (size_t)(ks*32)*NV + n8;
    #pragma unroll 8
    for (int kk = 0; kk < 32; kk++) {
      uint4 raw = *(const uint4*)(wb + (size_t)kk*NV);
      float2 f0 = __half22float2(*(__half2*)&raw.x);
      float2 f1 = __half22float2(*(__half2*)&raw.y);
      float2 f2 = __half22float2(*(__half2*)&raw.z);
      float2 f3 = __half22float2(*(__half2*)&raw.w);
      #pragma unroll
      for (int m = 0; m < 4; m++) {
        float xv = sx[m*DM + ks*32 + kk];
        a[m][0] = fmaf(xv, f0.x, a[m][0]); a[m][1] = fmaf(xv, f0.y, a[m][1]);
        a[m][2] = fmaf(xv, f1.x, a[m][2]); a[m][3] = fmaf(xv, f1.y, a[m][3]);
        a[m][4] = fmaf(xv, f2.x, a[m][4]); a[m][5] = fmaf(xv, f2.y, a[m][5]);
        a[m][6] = fmaf(xv, f3.x, a[m][6]); a[m][7] = fmaf(xv, f3.y, a[m][7]);
      }
    }
    #pragma unroll
    for (int m = 0; m < 4; m++) {
      #pragma unroll
      for (int j = 0; j < 8; j++) red[ks*128 + c*8 + j] = a[m][j];
      __syncthreads();
      if (tid < 128) {
        float v = red[tid];
        #pragma unroll
        for (int k2 = 1; k2 < 16; k2++) v += red[k2*128 + tid];
        g_lg[(size_t)m*NV + t*128 + tid] = v;
        red2[tid] = v;
      }
      __syncthreads();
      if (tid < 32) {
        float mx = -3e38f; int mi = 0;
        #pragma unroll
        for (int j = 0; j < 4; j++) {
          float u = red2[j*32 + tid];
          int ui = j*32 + tid;
          if (u > mx || (u == mx && ui < mi)) { mx = u; mi = ui; }
        }
        #pragma unroll
        for (int off = 16; off; off >>= 1) {
          float omx = __shfl_xor_sync(0xffffffffu, mx, off);
          int omi = __shfl_xor_sync(0xffffffffu, mi, off);
          if (omx > mx || (omx == mx && omi < mi)) { mx = omx; mi = omi; }
        }
        if (tid == 0) { sr[64] = mx; ((int*)sr)[65] = mi; }
      }
      __syncthreads();
      float gm = sr[64];
      if (tid < 128) red2[tid] = expf(red2[tid] - gm);
      __syncthreads();
      if (tid < 32) {
        float s = red2[tid] + red2[32+tid] + red2[64+tid] + red2[96+tid];
        #pragma unroll
        for (int off = 16; off; off >>= 1) s += __shfl_xor_sync(0xffffffffu, s, off);
        if (tid == 0) {
          g_pm[m*256 + t] = gm;
          g_ps[m*256 + t] = s;
          g_pi[m*256 + t] = t*128 + ((int*)sr)[65];
        }
      }
      __syncthreads();
    }
  }
}

// merged: combine chunk stats, write probs to out AND backproj partials
__device__ void ph_sm2bp(const P& p, int it, int skipbp,
                         float* sx, float* sr, int bid, int nb, int tid) {
  {
    int w = tid >> 5, lane = tid & 31;
    if (w < 4) {
      float mx = -3e38f; int mi = 0;
      for (int j = lane; j < NLM; j += 32) {
        float u = g_pm[w*256 + j];
        int ui = g_pi[w*256 + j];
        if (u > mx || (u == mx && ui < mi)) { mx = u; mi = ui; }
      }
      #pragma unroll
      for (int off = 16; off; off >>= 1) {
        float omx = __shfl_xor_sync(0xffffffffu, mx, off);
        int omi = __shfl_xor_sync(0xffffffffu, mi, off);
        if (omx > mx || (omx == mx && omi < mi)) { mx = omx; mi = omi; }
      }
      float s = 0.f;
      for (int j = lane; j < NLM; j += 32) s += g_ps[w*256+j]*expf(g_pm[w*256+j] - mx);
      #pragma unroll
      for (int off = 16; off; off >>= 1) s += __shfl_xor_sync(0xffffffffu, s, off);
      if (lane == 0) { sr[512+w] = mx; sr[516+w] = 1.f/s; ((int*)sr)[520+w] = mi; }
    }
  }
  __syncthreads();
  const int CL = NV/16;
  int ntasks = 64 + BPT;
  for (int t = bid; t < ntasks; t += nb) {
    if (t < 64) {
      int b = t >> 4, ch = t & 15;
      float M = sr[512+b], inv = sr[516+b];
      const float* lg = g_lg + (size_t)b*NV + ch*CL;
      float* pd = p.out + ((size_t)b*NT + it)*NV + ch*CL;
      for (int i = tid; i < CL; i += 256) pd[i] = expf(lg[i] - M)*inv;
      if (ch == 0 && tid == 0 && p.wp)
        p.out[(size_t)NB*NT*NV + (size_t)b*NT + it] = (((int*)sr)[520+b] == 0) ? 1.f : 0.f;
    } else if (!skipbp) {
      int tt = t - 64;
      int kb = tt*BPC;
      int klen = NV - kb; if (klen > BPC) klen = BPC;
      if (klen <= 0) continue;
      for (int idx = tid; idx < 4*BPC; idx += 256) {
        int m = idx / BPC, k = idx - m*BPC;
        float v = 0.f;
        if (k < klen) v = expf(g_lg[(size_t)m*NV + kb + k] - sr[512+m]) * sr[516+m];
        sx[m*BPC + k] = v;
      }
      __syncthreads();
      int c = tid & 127, ks = tid >> 7;
      int k0 = ks*67, k1 = k0 + 67; if (k1 > klen) k1 = klen; if (k0 > klen) k0 = klen;
      float4 a[4];
      #pragma unroll
      for (int m = 0; m < 4; m++) a[m] = make_float4(0,0,0,0);
      #pragma unroll 4
      for (int k = k0; k < k1; k++) {
        uint2 raw = *(const uint2*)(g_embh + (size_t)(kb+k)*DM + c*4);
        float2 e0 = __half22float2(*(__half2*)&raw.x);
        float2 e1 = __half22float2(*(__half2*)&raw.y);
        #pragma unroll
        for (int m = 0; m < 4; m++) {
          float pm = sx[m*BPC + k];
          a[m].x = fmaf(pm, e0.x, a[m].x);
          a[m].y = fmaf(pm, e0.y, a[m].y);
          a[m].z = fmaf(pm, e1.x, a[m].z);
          a[m].w = fmaf(pm, e1.y, a[m].w);
        }
      }
      float4* xr4 = (float4*)(sx + 1024);
      if (ks == 1) {
        #pragma unroll
        for (int m = 0; m < 4; m++) xr4[c*4+m] = a[m];
      }
      __syncthreads();
      if (ks == 0) {
        #pragma unroll
        for (int m = 0; m < 4; m++) {
          float4 u = xr4[c*4+m];
          a[m].x += u.x; a[m].y += u.y; a[m].z += u.z; a[m].w += u.w;
          ((float4*)g_part)[(size_t)tt*512 + m*128 + c] = a[m];
        }
      }
      __syncthreads();
    }
  }
}

// reduce BPT backproj partials -> ye[t+1]; one warp per float4 output
__device__ void ph_redye(float* dst, int bid, int nb, int tid) {
  int gw = bid*8 + (tid >> 5), lane = tid & 31;
  if (gw >= 512) return;
  const float4* p4 = (const float4*)g_part;
  float4 v = make_float4(0,0,0,0);
  for (int t = lane; t < BPT; t += 32) {
    float4 u = p4[(size_t)t*512 + gw];
    v.x += u.x; v.y += u.y; v.z += u.z; v.w += u.w;
  }
  #pragma unroll
  for (int off = 16; off; off >>= 1) {
    v.x += __shfl_xor_sync(0xffffffffu, v.x, off);
    v.y += __shfl_xor_sync(0xffffffffu, v.y, off);
    v.z += __shfl_xor_sync(0xffffffffu, v.z, off);
    v.w += __shfl_xor_sync(0xffffffffu, v.w, off);
  }
  if (lane == 0) ((float4*)dst)[gw] = v;
}

// ---------------- the megakernel ------------------------------------------
__global__ void __launch_bounds__(256, 2) mega(P p, int nb) {
  __shared__ float sx[4*FF + 256];  // 33 KB
  __shared__ float sr[1024];        // 4 KB
  __shared__ unsigned sg;
  int tid = threadIdx.x, bid = blockIdx.x;
  if (tid == 0) sg = 0;
  __syncthreads();

  // startup: fp16 conversions (lm + emb) + embedding
  conv1(p.lm,  g_lmh,  (size_t)DM*NV/4, bid, nb, tid);
  conv1(p.emb, g_embh, (size_t)NV*DM/4, bid, nb, tid);
  ph_embed(p, bid, nb, tid);                                          gbar(nb,&sg);

  // ---------------- encoder (fp32) ----------------
  for (int l = 0; l < NL; l++) {
    size_t o2 = (size_t)l*DM*DM, of = (size_t)l*DM*FF;
    ph_rms(g_x, p.eln1 + (size_t)l*DM, g_h, NB*SS, sr, bid, nb, tid); gbar(nb,&sg);
    { const float* Ws[3] = { p.ewq+o2, p.ewk+o2, p.ewv+o2 };
      float* Cs[3] = { g_q, g_k, g_v };
      ph_gemm(g_h, Ws, Cs, 3, NB*SS, DM, DM, 0, 1, nullptr, sx, bid, nb, tid); }
    gbar(nb,&sg);
    ph_attn(g_q, g_k, g_v, g_att, SS, SS, (long long)SS*DM, (long long)DM,
            p.mask, NB*SS*NH, sr, bid, nb, tid);                      gbar(nb,&sg);
    { const float* Ws[1] = { p.ewo+o2 }; float* Cs[1] = { g_x };
      ph_gemm(g_att, Ws, Cs, 1, NB*SS, DM, DM, 2, 1, nullptr, sx, bid, nb, tid); }
    gbar(nb,&sg);
    ph_rms(g_x, p.eln2 + (size_t)l*DM, g_h, NB*SS, sr, bid, nb, tid); gbar(nb,&sg);
    { const float* Ws[1] = { p.ew1+of }; float* Cs[1] = { g_f };
      ph_gemm(g_h, Ws, Cs, 1, NB*SS, FF, DM, 1, 1, nullptr, sx, bid, nb, tid); }
    gbar(nb,&sg);
    { const float* Ws[1] = { p.ew2+of }; float* Cs[1] = { nullptr };
      ph_gemm(g_f, Ws, Cs, 1, NB*SS, DM, FF, 0, 4, g_gp, sx, bid, nb, tid); }
    gbar(nb,&sg);
    ph_gred(g_x, g_gp, NB*SS, DM, 4, 2, bid, nb, tid);                gbar(nb,&sg);
  }
  ph_rms(g_x, p.elnf, g_hs, NB*SS, sr, bid, nb, tid);                 gbar(nb,&sg);
  { const float* Ws[4] = { p.dck, p.dcv, p.dck + (size_t)DM*DM, p.dcv + (size_t)DM*DM };
    float* Cs[4] = { g_ck, g_cv, g_ck + (size_t)NB*SS*DM, g_cv + (size_t)NB*SS*DM };
    ph_gemm(g_hs, Ws, Cs, 4, NB*SS, DM, DM, 0, 1, nullptr, sx, bid, nb, tid); }
  gbar(nb,&sg);

  // ---------------- decoder: 16 steps, 6 barriers per layer ----------------
  for (int it = 0; it < NT; it++) {
    const float* xin = g_ye + (size_t)it*NB*DM;
    for (int l = 0; l < NL; l++) {
      size_t o2 = (size_t)l*DM*DM, of = (size_t)l*DM*FF;
      const float* lx  = (l == 0) ? xin : g_xd3;
      const float* lvp = (l == 0) ? nullptr : g_vp;
      // qkv: stage (fold prev-layer w2 partials) -> writes x_eff to g_xd
      { const float* Ws[3] = { p.dsq+o2, p.dsk+o2, p.dsv+o2 };
        float* Os[3] = { g_qd,
                         g_sk + ((size_t)l*(NT+1) + it)*NB*DM,
                         g_sv + ((size_t)l*(NT+1) + it)*NB*DM };
        ph_gemv(lx, lvp, 4, g_xd, Ws, Os, 3, DM, DM, p.dln1 + (size_t)l*DM,
                0, 1, nullptr, sx, sr, bid, nb, tid); }
      gbar(nb,&sg);
      // fused self-attention + head-sliced so partials -> g_sop
      ph_attnso(g_qd, g_sk + (size_t)l*(NT+1)*NB*DM, g_sv + (size_t)l*(NT+1)*NB*DM,
                it+1, (long long)DM, (long long)NB*DM, nullptr,
                p.dso+o2, g_sop, sx, sr, bid, tid);
      gbar(nb,&sg);
      // cq: stage g_xd + fold sop(8) -> xr1 to g_xd2, rms(ln2) -> cq gemv
      { const float* Ws[1] = { p.dcq+o2 }; float* Os[1] = { g_qd };
        ph_gemv(g_xd, g_sop, 8, g_xd2, Ws, Os, 1, DM, DM, p.dln2 + (size_t)l*DM,
                0, 1, nullptr, sx, sr, bid, nb, tid); }
      gbar(nb,&sg);
      // fused cross-attention + head-sliced co partials -> g_sop
      ph_attnso(g_qd, g_ck + (size_t)l*NB*SS*DM, g_cv + (size_t)l*NB*SS*DM,
                SS, (long long)SS*DM, (long long)DM, p.mask,
                p.dco+o2, g_sop, sx, sr, bid, tid);
      gbar(nb,&sg);
      // w1: stage g_xd2 + fold cop(8) -> xr2 to g_xd3, rms(ln3) -> relu gemv
      { const float* Ws[1] = { p.dw1+of }; float* Os[1] = { g_fd };
        ph_gemv(g_xd2, g_sop, 8, g_xd3, Ws, Os, 1, FF, DM, p.dln3 + (size_t)l*DM,
                1, 1, nullptr, sx, sr, bid, nb, tid); }
      gbar(nb,&sg);
      // w2 -> block-ksplit partials g_vp (folded by next consumer)
      { const float* Ws[1] = { p.dw2+of }; float* Os[1] = { nullptr };
        ph_gemv(g_fd, nullptr, 0, nullptr, Ws, Os, 1, DM, FF, nullptr,
                0, 4, g_vp, sx, sr, bid, nb, tid); }
      gbar(nb,&sg);
    }
    ph_lmgemv(g_xd3, g_vp, p.dlnf, sx, sr, bid, nb, tid);
    gbar(nb,&sg);
    ph_sm2bp(p, it, it == NT-1, sx, sr, bid, nb, tid);
    if (it < NT-1) {
      gbar(nb,&sg);
      ph_redye(g_ye + (size_t)(it+1)*NB*DM, bid, nb, tid);
    }
    gbar(nb,&sg);
  }
  if (bid == 0 && tid == 0) {
    unsigned z = 0;
    asm volatile("st.release.gpu.u32 [%0], %1;" :: "l"(&g_cnt), "r"(z) : "memory");
  }
}

// ---------------- host ------------------------------------------------------
extern "C" void kernel_launch(void* const* d_in, const int* in_sizes, int n_in,
                              void* d_out, int out_size) {
  P p;
  p.ids   = (const int*)  d_in[0];
  p.mask  = (const float*)d_in[1];
  p.emb   = (const float*)d_in[2];
  p.ewq   = (const float*)d_in[3];
  p.ewk   = (const float*)d_in[4];
  p.ewv   = (const float*)d_in[5];
  p.ewo   = (const float*)d_in[6];
  p.eln1  = (const float*)d_in[7];
  p.ew1   = (const float*)d_in[8];
  p.ew2   = (const float*)d_in[9];
  p.eln2  = (const float*)d_in[10];
  p.elnf  = (const float*)d_in[11];
  p.dsq   = (const float*)d_in[12];
  p.dsk   = (const float*)d_in[13];
  p.dsv   = (const float*)d_in[14];
  p.dso   = (const float*)d_in[15];
  p.dln1  = (const float*)d_in[16];
  p.dcq   = (const float*)d_in[17];
  p.dck   = (const float*)d_in[18];
  p.dcv   = (const float*)d_in[19];
  p.dco   = (const float*)d_in[20];
  p.dln2  = (const float*)d_in[21];
  p.dw1   = (const float*)d_in[22];
  p.dw2   = (const float*)d_in[23];
  p.dln3  = (const float*)d_in[24];
  p.dlnf  = (const float*)d_in[25];
  p.lm    = (const float*)d_in[26];
  p.out   = (float*)d_out;
  p.wp    = (out_size > NB*NT*NV) ? 1 : 0;

  int dev = 0; cudaGetDevice(&dev);
  int sms = 0; cudaDeviceGetAttribute(&sms, cudaDevAttrMultiProcessorCount, dev);
  int nb = 2*sms;
  mega<<<nb, 256>>>(p, nb);
}